// round 1
// baseline (speedup 1.0000x reference)
#include <cuda_runtime.h>
#include <cuda_bf16.h>
#include <cstdint>

#define B_ 8
#define N_ 2048
#define D_ 2048
#define E_ 256
#define M_TOTAL (B_*N_)   // 16384

// Scratch (device globals: no allocation allowed)
__device__ float g_Q[M_TOTAL*E_];
__device__ float g_K[M_TOTAL*E_];
__device__ float g_V[M_TOTAL*E_];
__device__ float g_xsum[B_*D_];
__device__ float g_S[B_*E_];

static __device__ __forceinline__ unsigned smem_u32(const void* p){
  return (unsigned)__cvta_generic_to_shared(p);
}
static __device__ __forceinline__ void cp16(unsigned dst, const void* src){
  asm volatile("cp.async.cg.shared.global [%0], [%1], 16;\n" :: "r"(dst), "l"(src));
}
static __device__ __forceinline__ void cp_commit(){
  asm volatile("cp.async.commit_group;\n");
}
template<int N> static __device__ __forceinline__ void cp_wait(){
  asm volatile("cp.async.wait_group %0;\n" :: "n"(N));
}
static __device__ __forceinline__ void mma_tf32(float* c, const unsigned* a, const unsigned* b){
  asm volatile("mma.sync.aligned.m16n8k8.row.col.f32.tf32.tf32.f32 "
    "{%0,%1,%2,%3}, {%4,%5,%6,%7}, {%8,%9}, {%0,%1,%2,%3};\n"
    : "+f"(c[0]), "+f"(c[1]), "+f"(c[2]), "+f"(c[3])
    : "r"(a[0]), "r"(a[1]), "r"(a[2]), "r"(a[3]), "r"(b[0]), "r"(b[1]));
}

// ---------------- Kernel A: per-batch column sums of x ----------------
__global__ void k_rowsum(const float* __restrict__ x){
  int b = blockIdx.y;
  int d = blockIdx.x*256 + threadIdx.x;
  const float* p = x + (size_t)b*N_*D_ + d;
  float s0=0.f,s1=0.f,s2=0.f,s3=0.f;
  for(int n=0;n<N_;n+=4){
    s0 += p[(size_t)n*D_];
    s1 += p[(size_t)(n+1)*D_];
    s2 += p[(size_t)(n+2)*D_];
    s3 += p[(size_t)(n+3)*D_];
  }
  g_xsum[b*D_+d] = (s0+s1)+(s2+s3);
}

// ---------------- Kernel B: S[b] = xsum[b] @ Wv + 2048*bv (exact fp32) ----------------
__global__ void k_sproj(const float* __restrict__ Wv, const float* __restrict__ bv){
  __shared__ float xs[D_];
  int b = blockIdx.x, e = threadIdx.x;
  for(int i=e;i<D_;i+=256) xs[i] = g_xsum[b*D_+i];
  __syncthreads();
  float a0=0.f,a1=0.f,a2=0.f,a3=0.f;
  for(int d=0;d<D_;d+=4){
    a0 += xs[d  ]*Wv[(size_t)(d  )*E_+e];
    a1 += xs[d+1]*Wv[(size_t)(d+1)*E_+e];
    a2 += xs[d+2]*Wv[(size_t)(d+2)*E_+e];
    a3 += xs[d+3]*Wv[(size_t)(d+3)*E_+e];
  }
  g_S[b*E_+e] = (a0+a1)+(a2+a3) + 2048.0f*bv[e];
}

// ---------------- Kernel C: Q/K/V = x @ W + b  (tf32 mma, double-buffered cp.async) ----------------
#define C_BM 128
#define C_BN 64
#define C_BK 32
#define C_AS 36
#define C_BS 72
#define C_SMEM ((2*C_BM*C_AS + 2*C_BK*C_BS)*4)

__global__ __launch_bounds__(256) void k_qkv(
    const float* __restrict__ x,
    const float* __restrict__ Wq, const float* __restrict__ bq,
    const float* __restrict__ Wk, const float* __restrict__ bk,
    const float* __restrict__ Wv, const float* __restrict__ bv)
{
  extern __shared__ float sm[];
  float* As = sm;                      // [2][128][36]
  float* Bs = sm + 2*C_BM*C_AS;        // [2][32][72]

  const float* W; const float* bias; float* outp;
  int z = blockIdx.z;
  if(z==0){ W=Wq; bias=bq; outp=g_Q; }
  else if(z==1){ W=Wk; bias=bk; outp=g_K; }
  else { W=Wv; bias=bv; outp=g_V; }

  int m0 = blockIdx.x*C_BM;
  int n0 = blockIdx.y*C_BN;
  int tid = threadIdx.x;
  int w = tid>>5, lane = tid&31, g = lane>>2, tg = lane&3;
  int wm = w&3, wn = w>>2;   // warp tile 32x32

  float acc[2][4][4];
  #pragma unroll
  for(int mt=0;mt<2;mt++)
    #pragma unroll
    for(int nt=0;nt<4;nt++)
      #pragma unroll
      for(int i=0;i<4;i++) acc[mt][nt][i]=0.f;

  // prologue: stage 0
  {
    unsigned da = smem_u32(As);
    #pragma unroll
    for(int j=0;j<4;j++){
      int idx = tid + 256*j; int row = idx>>3, c4 = idx&7;
      cp16(da + (unsigned)(row*C_AS + c4*4)*4, x + ((size_t)(m0+row)*D_ + c4*4));
    }
    unsigned db = smem_u32(Bs);
    #pragma unroll
    for(int j=0;j<2;j++){
      int idx = tid + 256*j; int row = idx>>4, c4 = idx&15;
      cp16(db + (unsigned)(row*C_BS + c4*4)*4, W + ((size_t)row*E_ + n0 + c4*4));
    }
    cp_commit();
  }

  const int KT = D_/C_BK;  // 64
  for(int kt=0; kt<KT; kt++){
    int cur = kt&1;
    if(kt+1 < KT){
      int nxt = cur^1;
      unsigned da = smem_u32(As + nxt*C_BM*C_AS);
      #pragma unroll
      for(int j=0;j<4;j++){
        int idx = tid + 256*j; int row = idx>>3, c4 = idx&7;
        cp16(da + (unsigned)(row*C_AS + c4*4)*4,
             x + ((size_t)(m0+row)*D_ + (kt+1)*C_BK + c4*4));
      }
      unsigned db = smem_u32(Bs + nxt*C_BK*C_BS);
      #pragma unroll
      for(int j=0;j<2;j++){
        int idx = tid + 256*j; int row = idx>>4, c4 = idx&15;
        cp16(db + (unsigned)(row*C_BS + c4*4)*4,
             W + ((size_t)((kt+1)*C_BK+row)*E_ + n0 + c4*4));
      }
      cp_commit();
      cp_wait<1>();
    } else {
      cp_wait<0>();
    }
    __syncthreads();

    const float* Ac = As + cur*C_BM*C_AS;
    const float* Bc = Bs + cur*C_BK*C_BS;
    #pragma unroll
    for(int kk=0;kk<4;kk++){
      unsigned a[2][4];
      #pragma unroll
      for(int mt=0;mt<2;mt++){
        int r = wm*32 + mt*16;
        a[mt][0] = __float_as_uint(Ac[(r+g  )*C_AS + kk*8+tg  ]);
        a[mt][1] = __float_as_uint(Ac[(r+g+8)*C_AS + kk*8+tg  ]);
        a[mt][2] = __float_as_uint(Ac[(r+g  )*C_AS + kk*8+tg+4]);
        a[mt][3] = __float_as_uint(Ac[(r+g+8)*C_AS + kk*8+tg+4]);
      }
      unsigned b[4][2];
      #pragma unroll
      for(int nt=0;nt<4;nt++){
        int c = wn*32 + nt*8 + g;
        b[nt][0] = __float_as_uint(Bc[(kk*8+tg  )*C_BS + c]);
        b[nt][1] = __float_as_uint(Bc[(kk*8+tg+4)*C_BS + c]);
      }
      #pragma unroll
      for(int mt=0;mt<2;mt++)
        #pragma unroll
        for(int nt=0;nt<4;nt++)
          mma_tf32(acc[mt][nt], a[mt], b[nt]);
    }
    __syncthreads();
  }

  // epilogue: +bias, store fp32
  #pragma unroll
  for(int mt=0;mt<2;mt++){
    int r0 = m0 + wm*32 + mt*16 + g;
    #pragma unroll
    for(int nt=0;nt<4;nt++){
      int c = n0 + wn*32 + nt*8 + 2*tg;
      float b0 = bias[c], b1 = bias[c+1];
      float2 v0 = make_float2(acc[mt][nt][0]+b0, acc[mt][nt][1]+b1);
      float2 v1 = make_float2(acc[mt][nt][2]+b0, acc[mt][nt][3]+b1);
      *(float2*)(outp + (size_t)r0*E_ + c)     = v0;
      *(float2*)(outp + (size_t)(r0+8)*E_ + c) = v1;
    }
  }
}

// ---------------- Kernel D: flash attention with e = 1 + p decomposition ----------------
#define A_BM 64
#define A_BN 64
#define QKS 264
#define PS_ 76
#define A_SMEM ((3*64*QKS + 64*PS_ + 64 + 256)*4)

__global__ __launch_bounds__(256,1) void k_attn(float* __restrict__ out){
  extern __shared__ float sm[];
  float* Qs = sm;                   // [64][264]
  float* Ks = Qs + 64*QKS;          // [64][264]
  float* Vs = Ks + 64*QKS;          // [64][264]
  float* Ps = Vs + 64*QKS;          // [64][76]
  float* Zs = Ps + 64*PS_;          // [64]
  float* Ss = Zs + 64;              // [256]

  int bb = blockIdx.y;
  int n0 = blockIdx.x*A_BM;
  int tid = threadIdx.x;
  int w = tid>>5, lane = tid&31, g = lane>>2, tg = lane&3;
  int swm = w&3, swn = w>>2;   // scores: 4x2 warp grid, warp tile 16x32
  int owm = w>>2, own = w&3;   // output: 2x4 warp grid, warp tile 32x64

  if(tid < 64) Zs[tid] = 0.0f;
  Ss[tid] = g_S[bb*E_ + tid];

  // load Q tile once
  {
    unsigned dq = smem_u32(Qs);
    const float* src = g_Q + ((size_t)(bb*N_ + n0))*E_;
    #pragma unroll
    for(int j=0;j<16;j++){
      int idx = tid + 256*j; int row = idx>>6, c4 = idx&63;
      cp16(dq + (unsigned)(row*QKS + c4*4)*4, src + (size_t)row*E_ + c4*4);
    }
    cp_commit();
  }

  float oacc[2][8][4];
  #pragma unroll
  for(int mt=0;mt<2;mt++)
    #pragma unroll
    for(int nt=0;nt<8;nt++)
      #pragma unroll
      for(int i=0;i<4;i++) oacc[mt][nt][i]=0.f;

  cp_wait<0>();
  __syncthreads();

  for(int kb=0; kb<N_/A_BN; kb++){
    int m0 = kb*A_BN;
    // load K, V tiles
    {
      unsigned dk = smem_u32(Ks), dv = smem_u32(Vs);
      const float* ksrc = g_K + ((size_t)(bb*N_ + m0))*E_;
      const float* vsrc = g_V + ((size_t)(bb*N_ + m0))*E_;
      #pragma unroll
      for(int j=0;j<16;j++){
        int idx = tid + 256*j; int row = idx>>6, c4 = idx&63;
        cp16(dk + (unsigned)(row*QKS + c4*4)*4, ksrc + (size_t)row*E_ + c4*4);
        cp16(dv + (unsigned)(row*QKS + c4*4)*4, vsrc + (size_t)row*E_ + c4*4);
      }
      cp_commit();
      cp_wait<0>();
      __syncthreads();
    }

    // s = Q @ K^T  (warp tile 16x32)
    float sc[4][4];
    #pragma unroll
    for(int nt=0;nt<4;nt++)
      #pragma unroll
      for(int i=0;i<4;i++) sc[nt][i]=0.f;

    #pragma unroll
    for(int kk=0;kk<32;kk++){
      unsigned a[4];
      int r = swm*16;
      a[0] = __float_as_uint(Qs[(r+g  )*QKS + kk*8+tg  ]);
      a[1] = __float_as_uint(Qs[(r+g+8)*QKS + kk*8+tg  ]);
      a[2] = __float_as_uint(Qs[(r+g  )*QKS + kk*8+tg+4]);
      a[3] = __float_as_uint(Qs[(r+g+8)*QKS + kk*8+tg+4]);
      #pragma unroll
      for(int nt=0;nt<4;nt++){
        unsigned b[2];
        int c = swn*32 + nt*8 + g;
        b[0] = __float_as_uint(Ks[c*QKS + kk*8+tg  ]);
        b[1] = __float_as_uint(Ks[c*QKS + kk*8+tg+4]);
        mma_tf32(sc[nt], a, b);
      }
    }

    // p = expm1(sigmoid(s)/16); Z row sums
    float zlo=0.f, zhi=0.f;
    #pragma unroll
    for(int nt=0;nt<4;nt++){
      #pragma unroll
      for(int i=0;i<4;i++){
        float s = sc[nt][i];
        float sig = __fdividef(1.0f, 1.0f + __expf(-s));
        float gg = 0.0625f * sig;
        float p = gg*fmaf(gg, fmaf(gg, fmaf(gg, 0.041666668f, 0.16666667f), 0.5f), 1.0f);
        sc[nt][i] = p;
      }
      zlo += sc[nt][0]+sc[nt][1];
      zhi += sc[nt][2]+sc[nt][3];
    }
    zlo += __shfl_xor_sync(0xffffffffu, zlo, 1);
    zlo += __shfl_xor_sync(0xffffffffu, zlo, 2);
    zhi += __shfl_xor_sync(0xffffffffu, zhi, 1);
    zhi += __shfl_xor_sync(0xffffffffu, zhi, 2);
    if(tg==0){
      atomicAdd(&Zs[swm*16+g],   zlo);
      atomicAdd(&Zs[swm*16+g+8], zhi);
    }
    // store p tile
    #pragma unroll
    for(int nt=0;nt<4;nt++){
      int c = swn*32 + nt*8 + 2*tg;
      *(float2*)&Ps[(swm*16+g  )*PS_ + c] = make_float2(sc[nt][0], sc[nt][1]);
      *(float2*)&Ps[(swm*16+g+8)*PS_ + c] = make_float2(sc[nt][2], sc[nt][3]);
    }
    __syncthreads();

    // out += p @ V  (warp tile 32x64)
    #pragma unroll
    for(int kk=0;kk<8;kk++){
      unsigned a[2][4];
      #pragma unroll
      for(int mt=0;mt<2;mt++){
        int r = owm*32 + mt*16;
        a[mt][0] = __float_as_uint(Ps[(r+g  )*PS_ + kk*8+tg  ]);
        a[mt][1] = __float_as_uint(Ps[(r+g+8)*PS_ + kk*8+tg  ]);
        a[mt][2] = __float_as_uint(Ps[(r+g  )*PS_ + kk*8+tg+4]);
        a[mt][3] = __float_as_uint(Ps[(r+g+8)*PS_ + kk*8+tg+4]);
      }
      #pragma unroll
      for(int nt=0;nt<8;nt++){
        unsigned b[2];
        int c = own*64 + nt*8 + g;
        b[0] = __float_as_uint(Vs[(kk*8+tg  )*QKS + c]);
        b[1] = __float_as_uint(Vs[(kk*8+tg+4)*QKS + c]);
        #pragma unroll
        for(int mt=0;mt<2;mt++)
          mma_tf32(oacc[mt][nt], a[mt], b);
      }
    }
    __syncthreads();
  }

  // epilogue: out = (S + acc) / (2048 + Zsum)
  #pragma unroll
  for(int mt=0;mt<2;mt++){
    int r = owm*32 + mt*16 + g;
    float rz0 = __fdividef(1.0f, 2048.0f + Zs[r]);
    float rz1 = __fdividef(1.0f, 2048.0f + Zs[r+8]);
    #pragma unroll
    for(int nt=0;nt<8;nt++){
      int c = own*64 + nt*8 + 2*tg;
      float s0 = Ss[c], s1 = Ss[c+1];
      float2 y0 = make_float2((s0+oacc[mt][nt][0])*rz0, (s1+oacc[mt][nt][1])*rz0);
      float2 y1 = make_float2((s0+oacc[mt][nt][2])*rz1, (s1+oacc[mt][nt][3])*rz1);
      *(float2*)(out + ((size_t)(bb*N_ + n0 + r  ))*E_ + c) = y0;
      *(float2*)(out + ((size_t)(bb*N_ + n0 + r+8))*E_ + c) = y1;
    }
  }
}

extern "C" void kernel_launch(void* const* d_in, const int* in_sizes, int n_in,
                              void* d_out, int out_size){
  const float* x  = (const float*)d_in[0];
  const float* Wq = (const float*)d_in[1];
  const float* bq = (const float*)d_in[2];
  const float* Wk = (const float*)d_in[3];
  const float* bk = (const float*)d_in[4];
  const float* Wv = (const float*)d_in[5];
  const float* bv = (const float*)d_in[6];
  float* out = (float*)d_out;

  cudaFuncSetAttribute(k_qkv,  cudaFuncAttributeMaxDynamicSharedMemorySize, C_SMEM);
  cudaFuncSetAttribute(k_attn, cudaFuncAttributeMaxDynamicSharedMemorySize, A_SMEM);

  k_rowsum<<<dim3(8, B_), 256>>>(x);
  k_sproj<<<B_, 256>>>(Wv, bv);
  k_qkv<<<dim3(M_TOTAL/C_BM, E_/C_BN, 3), 256, C_SMEM>>>(x, Wq, bq, Wk, bk, Wv, bv);
  k_attn<<<dim3(N_/A_BM, B_), 256, A_SMEM>>>(out);
}

// round 2
// speedup vs baseline: 1.8951x; 1.8951x over previous
#include <cuda_runtime.h>
#include <cuda_bf16.h>
#include <cstdint>

#define B_ 8
#define N_ 2048
#define D_ 2048
#define E_ 256
#define M_TOTAL (B_*N_)   // 16384

// ---------------- scratch (device globals; no allocation allowed) ----------------
__device__ __nv_bfloat16 g_xb[M_TOTAL*D_];     // x in bf16
__device__ __nv_bfloat16 g_Wqb[D_*E_];
__device__ __nv_bfloat16 g_Wkb[D_*E_];
__device__ __nv_bfloat16 g_Wvb[D_*E_];
__device__ __nv_bfloat16 g_Q[M_TOTAL*E_];
__device__ __nv_bfloat16 g_K[M_TOTAL*E_];
__device__ __nv_bfloat16 g_V[M_TOTAL*E_];
__device__ float g_xpart[8*B_*D_];             // partial column sums of x
__device__ float g_S[B_*E_];                   // exact fp32 sum_m v_m per batch

static __device__ __forceinline__ unsigned smem_u32(const void* p){
  return (unsigned)__cvta_generic_to_shared(p);
}
static __device__ __forceinline__ void cp16(unsigned dst, const void* src){
  asm volatile("cp.async.cg.shared.global [%0], [%1], 16;\n" :: "r"(dst), "l"(src));
}
static __device__ __forceinline__ void cp_commit(){
  asm volatile("cp.async.commit_group;\n");
}
template<int N> static __device__ __forceinline__ void cp_wait(){
  asm volatile("cp.async.wait_group %0;\n" :: "n"(N));
}
static __device__ __forceinline__ void ldsm_x4(unsigned* r, unsigned addr){
  asm volatile("ldmatrix.sync.aligned.m8n8.x4.shared.b16 {%0,%1,%2,%3}, [%4];\n"
    : "=r"(r[0]),"=r"(r[1]),"=r"(r[2]),"=r"(r[3]) : "r"(addr));
}
static __device__ __forceinline__ void ldsm_x4_t(unsigned* r, unsigned addr){
  asm volatile("ldmatrix.sync.aligned.m8n8.x4.trans.shared.b16 {%0,%1,%2,%3}, [%4];\n"
    : "=r"(r[0]),"=r"(r[1]),"=r"(r[2]),"=r"(r[3]) : "r"(addr));
}
static __device__ __forceinline__ void mma_bf16(float* c, const unsigned* a, unsigned b0, unsigned b1){
  asm volatile("mma.sync.aligned.m16n8k16.row.col.f32.bf16.bf16.f32 "
    "{%0,%1,%2,%3}, {%4,%5,%6,%7}, {%8,%9}, {%0,%1,%2,%3};\n"
    : "+f"(c[0]), "+f"(c[1]), "+f"(c[2]), "+f"(c[3])
    : "r"(a[0]), "r"(a[1]), "r"(a[2]), "r"(a[3]), "r"(b0), "r"(b1));
}

// ---------------- Kernel: fp32 -> bf16 conversion (vectorized) ----------------
__global__ void k_cvt(const float4* __restrict__ src, __nv_bfloat162* __restrict__ dst, int n4){
  int i = blockIdx.x*blockDim.x + threadIdx.x;
  if(i < n4){
    float4 v = src[i];
    dst[2*i  ] = __floats2bfloat162_rn(v.x, v.y);
    dst[2*i+1] = __floats2bfloat162_rn(v.z, v.w);
  }
}

// ---------------- Kernel A: per-batch partial column sums of x (fp32 exact path) ----------------
__global__ void k_rowsum(const float* __restrict__ x){
  int b = blockIdx.y;
  int ns = blockIdx.z;              // 8-way split over N
  int d = blockIdx.x*256 + threadIdx.x;
  const float* p = x + (size_t)b*N_*D_ + (size_t)ns*(N_/8)*D_ + d;
  float s0=0.f,s1=0.f,s2=0.f,s3=0.f;
  for(int n=0;n<N_/8;n+=4){
    s0 += p[(size_t)n*D_];
    s1 += p[(size_t)(n+1)*D_];
    s2 += p[(size_t)(n+2)*D_];
    s3 += p[(size_t)(n+3)*D_];
  }
  g_xpart[(ns*B_ + b)*D_ + d] = (s0+s1)+(s2+s3);
}

// ---------------- Kernel B: S[b] = xsum[b] @ Wv + 2048*bv (exact fp32) ----------------
__global__ void k_sproj(const float* __restrict__ Wv, const float* __restrict__ bv){
  __shared__ float xs[D_];
  int b = blockIdx.x, e = threadIdx.x;
  for(int i=e;i<D_;i+=256){
    float s = 0.f;
    #pragma unroll
    for(int ns=0;ns<8;ns++) s += g_xpart[(ns*B_ + b)*D_ + i];
    xs[i] = s;
  }
  __syncthreads();
  float a0=0.f,a1=0.f,a2=0.f,a3=0.f;
  for(int d=0;d<D_;d+=4){
    a0 += xs[d  ]*Wv[(size_t)(d  )*E_+e];
    a1 += xs[d+1]*Wv[(size_t)(d+1)*E_+e];
    a2 += xs[d+2]*Wv[(size_t)(d+2)*E_+e];
    a3 += xs[d+3]*Wv[(size_t)(d+3)*E_+e];
  }
  g_S[b*E_+e] = (a0+a1)+(a2+a3) + 2048.0f*bv[e];
}

// ---------------- Kernel C: Q/K/V = xb @ Wb + b  (bf16 m16n8k16 + ldmatrix) ----------------
#define C_BM 128
#define C_BN 128
#define C_BK 32
#define C_AST 40    // elements per A row (80B, conflict-free LDSM)
#define C_BST 136   // elements per B row (272B, conflict-free LDSM.T)
#define C_SMEM ((2*C_BM*C_AST + 2*C_BK*C_BST)*2)

__global__ __launch_bounds__(256) void k_qkv(
    const float* __restrict__ bq, const float* __restrict__ bk, const float* __restrict__ bv)
{
  extern __shared__ __nv_bfloat16 smc[];
  __nv_bfloat16* As = smc;                   // [2][128][40]
  __nv_bfloat16* Bs = smc + 2*C_BM*C_AST;    // [2][32][136]

  const __nv_bfloat16* W; const float* bias; __nv_bfloat16* outp;
  int z = blockIdx.z;
  if(z==0){ W=g_Wqb; bias=bq; outp=g_Q; }
  else if(z==1){ W=g_Wkb; bias=bk; outp=g_K; }
  else { W=g_Wvb; bias=bv; outp=g_V; }

  int m0 = blockIdx.x*C_BM;
  int n0 = blockIdx.y*C_BN;
  int tid = threadIdx.x;
  int w = tid>>5, lane = tid&31, g = lane>>2, tg = lane&3;
  int wm = w&3, wn = w>>2;   // warp tile 32(m) x 64(n)

  float acc[2][8][4];
  #pragma unroll
  for(int mt=0;mt<2;mt++)
    #pragma unroll
    for(int nc=0;nc<8;nc++)
      #pragma unroll
      for(int i=0;i<4;i++) acc[mt][nc][i]=0.f;

  unsigned as_base = smem_u32(As);
  unsigned bs_base = smem_u32(Bs);

  // prologue: stage 0
  {
    #pragma unroll
    for(int j=0;j<2;j++){
      int idx = tid + 256*j; int row = idx>>2, c16 = idx&3;
      cp16(as_base + (unsigned)(row*80 + c16*16), g_xb + ((size_t)(m0+row)*D_ + c16*8));
    }
    #pragma unroll
    for(int j=0;j<2;j++){
      int idx = tid + 256*j; int row = idx>>4, c16 = idx&15;
      cp16(bs_base + (unsigned)(row*272 + c16*16), W + ((size_t)row*E_ + n0 + c16*8));
    }
    cp_commit();
  }

  const int KT = D_/C_BK;  // 64
  for(int kt=0; kt<KT; kt++){
    int cur = kt&1;
    if(kt+1 < KT){
      int nxt = cur^1;
      unsigned da = as_base + (unsigned)(nxt*C_BM*C_AST*2);
      #pragma unroll
      for(int j=0;j<2;j++){
        int idx = tid + 256*j; int row = idx>>2, c16 = idx&3;
        cp16(da + (unsigned)(row*80 + c16*16),
             g_xb + ((size_t)(m0+row)*D_ + (kt+1)*C_BK + c16*8));
      }
      unsigned db = bs_base + (unsigned)(nxt*C_BK*C_BST*2);
      #pragma unroll
      for(int j=0;j<2;j++){
        int idx = tid + 256*j; int row = idx>>4, c16 = idx&15;
        cp16(db + (unsigned)(row*272 + c16*16),
             W + ((size_t)((kt+1)*C_BK+row)*E_ + n0 + c16*8));
      }
      cp_commit();
      cp_wait<1>();
    } else {
      cp_wait<0>();
    }
    __syncthreads();

    unsigned ac = as_base + (unsigned)(cur*C_BM*C_AST*2);
    unsigned bc = bs_base + (unsigned)(cur*C_BK*C_BST*2);
    #pragma unroll
    for(int kc=0;kc<2;kc++){
      unsigned a[2][4];
      #pragma unroll
      for(int mt=0;mt<2;mt++){
        int row = wm*32 + mt*16 + (lane&15);
        int col = kc*16 + (lane>>4)*8;
        ldsm_x4(a[mt], ac + (unsigned)(row*80 + col*2));
      }
      #pragma unroll
      for(int nb=0;nb<4;nb++){
        unsigned r[4];
        int row = kc*16 + (lane&7) + ((lane>>3)&1)*8;
        int col = wn*64 + nb*16 + (lane>>4)*8;
        ldsm_x4_t(r, bc + (unsigned)(row*272 + col*2));
        #pragma unroll
        for(int mt=0;mt<2;mt++){
          mma_bf16(acc[mt][2*nb  ], a[mt], r[0], r[1]);
          mma_bf16(acc[mt][2*nb+1], a[mt], r[2], r[3]);
        }
      }
    }
    __syncthreads();
  }

  // epilogue: +bias, store bf16
  #pragma unroll
  for(int mt=0;mt<2;mt++){
    int r0 = m0 + wm*32 + mt*16 + g;
    #pragma unroll
    for(int nc=0;nc<8;nc++){
      int c = n0 + wn*64 + nc*8 + 2*tg;
      float b0 = bias[c], b1 = bias[c+1];
      *(__nv_bfloat162*)(outp + (size_t)r0*E_ + c) =
        __floats2bfloat162_rn(acc[mt][nc][0]+b0, acc[mt][nc][1]+b1);
      *(__nv_bfloat162*)(outp + (size_t)(r0+8)*E_ + c) =
        __floats2bfloat162_rn(acc[mt][nc][2]+b0, acc[mt][nc][3]+b1);
    }
  }
}

// ---------------- Kernel D: flash attention, e = 1 + p decomposition, bf16 mma ----------------
#define A_BM 64
#define A_BN 64
#define QKST 264   // elements per Q/K/V row (528B)
#define PST  72    // elements per P row (144B)
// smem: Q[64*264] + K[2][64*264] + V[2][64*264] + P[64*72] + Z[64] + S[256]
#define A_Q_OFF 0
#define A_K_OFF (64*QKST)              // K buffers at K_OFF, K_OFF+64*QKST
#define A_V_OFF (3*64*QKST)
#define A_P_OFF (5*64*QKST)
#define A_SMEM_BF (5*64*QKST + 64*PST)
#define A_SMEM (A_SMEM_BF*2 + (64+256)*4)

__global__ __launch_bounds__(256,1) void k_attn(float* __restrict__ out){
  extern __shared__ __nv_bfloat16 sma[];
  __nv_bfloat16* Qs = sma + A_Q_OFF;
  __nv_bfloat16* Ks = sma + A_K_OFF;
  __nv_bfloat16* Vs = sma + A_V_OFF;
  __nv_bfloat16* Ps = sma + A_P_OFF;
  float* Zs = (float*)(sma + A_SMEM_BF);
  float* Ss = Zs + 64;

  int bb = blockIdx.y;
  int n0 = blockIdx.x*A_BM;
  int tid = threadIdx.x;
  int w = tid>>5, lane = tid&31, g = lane>>2, tg = lane&3;
  int swm = w&3, swn = w>>2;   // scores: warp tile 16(m) x 32(n)
  int owm = w>>2, own = w&3;   // output: warp tile 32(m) x 64(e)

  if(tid < 64) Zs[tid] = 0.0f;
  Ss[tid] = g_S[bb*E_ + tid];

  unsigned q_base = smem_u32(Qs);
  unsigned k_base = smem_u32(Ks);
  unsigned v_base = smem_u32(Vs);
  unsigned p_base = smem_u32(Ps);

  // prologue: Q tile + KV block 0, one group
  {
    const __nv_bfloat16* qsrc = g_Q + ((size_t)(bb*N_ + n0))*E_;
    const __nv_bfloat16* ksrc = g_K + ((size_t)bb*N_)*E_;
    const __nv_bfloat16* vsrc = g_V + ((size_t)bb*N_)*E_;
    #pragma unroll
    for(int j=0;j<8;j++){
      int idx = tid + 256*j; int row = idx>>5, c16 = idx&31;
      unsigned off = (unsigned)(row*528 + c16*16);
      size_t soff = (size_t)row*E_ + c16*8;
      cp16(q_base + off, qsrc + soff);
      cp16(k_base + off, ksrc + soff);
      cp16(v_base + off, vsrc + soff);
    }
    cp_commit();
  }

  float oacc[2][8][4];
  #pragma unroll
  for(int mt=0;mt<2;mt++)
    #pragma unroll
    for(int nc=0;nc<8;nc++)
      #pragma unroll
      for(int i=0;i<4;i++) oacc[mt][nc][i]=0.f;

  const int KB = N_/A_BN;  // 32
  for(int kb=0; kb<KB; kb++){
    int cur = kb&1;
    if(kb+1 < KB){
      int nxt = cur^1;
      unsigned dk = k_base + (unsigned)(nxt*64*QKST*2);
      unsigned dv = v_base + (unsigned)(nxt*64*QKST*2);
      const __nv_bfloat16* ksrc = g_K + ((size_t)(bb*N_ + (kb+1)*A_BN))*E_;
      const __nv_bfloat16* vsrc = g_V + ((size_t)(bb*N_ + (kb+1)*A_BN))*E_;
      #pragma unroll
      for(int j=0;j<8;j++){
        int idx = tid + 256*j; int row = idx>>5, c16 = idx&31;
        unsigned off = (unsigned)(row*528 + c16*16);
        size_t soff = (size_t)row*E_ + c16*8;
        cp16(dk + off, ksrc + soff);
        cp16(dv + off, vsrc + soff);
      }
      cp_commit();
      cp_wait<1>();
    } else {
      cp_wait<0>();
    }
    __syncthreads();

    unsigned kc_base = k_base + (unsigned)(cur*64*QKST*2);
    unsigned vc_base = v_base + (unsigned)(cur*64*QKST*2);

    // ---- s = Q @ K^T ----
    float sc[4][4];
    #pragma unroll
    for(int nc=0;nc<4;nc++)
      #pragma unroll
      for(int i=0;i<4;i++) sc[nc][i]=0.f;

    #pragma unroll
    for(int kc=0;kc<16;kc++){
      unsigned a[4];
      {
        int row = swm*16 + (lane&15);
        int col = kc*16 + (lane>>4)*8;
        ldsm_x4(a, q_base + (unsigned)(row*528 + col*2));
      }
      #pragma unroll
      for(int nb=0;nb<2;nb++){
        unsigned r[4];
        int row = swn*32 + nb*16 + (lane&15);
        int col = kc*16 + (lane>>4)*8;
        ldsm_x4(r, kc_base + (unsigned)(row*528 + col*2));
        mma_bf16(sc[2*nb  ], a, r[0], r[2]);
        mma_bf16(sc[2*nb+1], a, r[1], r[3]);
      }
    }

    // ---- p = expm1(sigmoid(s)/16); Z row sums; store P bf16 ----
    float zlo=0.f, zhi=0.f;
    #pragma unroll
    for(int nc=0;nc<4;nc++){
      #pragma unroll
      for(int i=0;i<4;i++){
        float s = sc[nc][i];
        float sig = __fdividef(1.0f, 1.0f + __expf(-s));
        float gg = 0.0625f * sig;
        sc[nc][i] = gg*fmaf(gg, fmaf(gg, fmaf(gg, 0.041666668f, 0.16666667f), 0.5f), 1.0f);
      }
      zlo += sc[nc][0]+sc[nc][1];
      zhi += sc[nc][2]+sc[nc][3];
    }
    zlo += __shfl_xor_sync(0xffffffffu, zlo, 1);
    zlo += __shfl_xor_sync(0xffffffffu, zlo, 2);
    zhi += __shfl_xor_sync(0xffffffffu, zhi, 1);
    zhi += __shfl_xor_sync(0xffffffffu, zhi, 2);
    if(tg==0){
      atomicAdd(&Zs[swm*16+g],   zlo);
      atomicAdd(&Zs[swm*16+g+8], zhi);
    }
    #pragma unroll
    for(int nc=0;nc<4;nc++){
      int c = swn*32 + nc*8 + 2*tg;
      *(__nv_bfloat162*)((char*)Ps + (swm*16+g  )*144 + c*2) =
        __floats2bfloat162_rn(sc[nc][0], sc[nc][1]);
      *(__nv_bfloat162*)((char*)Ps + (swm*16+g+8)*144 + c*2) =
        __floats2bfloat162_rn(sc[nc][2], sc[nc][3]);
    }
    __syncthreads();

    // ---- out += P @ V ----
    #pragma unroll
    for(int kc=0;kc<4;kc++){
      unsigned a[2][4];
      #pragma unroll
      for(int mt=0;mt<2;mt++){
        int row = owm*32 + mt*16 + (lane&15);
        int col = kc*16 + (lane>>4)*8;
        ldsm_x4(a[mt], p_base + (unsigned)(row*144 + col*2));
      }
      #pragma unroll
      for(int nb=0;nb<4;nb++){
        unsigned r[4];
        int row = kc*16 + (lane&7) + ((lane>>3)&1)*8;
        int col = own*64 + nb*16 + (lane>>4)*8;
        ldsm_x4_t(r, vc_base + (unsigned)(row*528 + col*2));
        #pragma unroll
        for(int mt=0;mt<2;mt++){
          mma_bf16(oacc[mt][2*nb  ], a[mt], r[0], r[1]);
          mma_bf16(oacc[mt][2*nb+1], a[mt], r[2], r[3]);
        }
      }
    }
    __syncthreads();
  }

  // epilogue: out = (S + acc) / (2048 + Z)
  #pragma unroll
  for(int mt=0;mt<2;mt++){
    int r = owm*32 + mt*16 + g;
    float rz0 = __fdividef(1.0f, 2048.0f + Zs[r]);
    float rz1 = __fdividef(1.0f, 2048.0f + Zs[r+8]);
    #pragma unroll
    for(int nc=0;nc<8;nc++){
      int c = own*64 + nc*8 + 2*tg;
      float s0 = Ss[c], s1 = Ss[c+1];
      float2 y0 = make_float2((s0+oacc[mt][nc][0])*rz0, (s1+oacc[mt][nc][1])*rz0);
      float2 y1 = make_float2((s0+oacc[mt][nc][2])*rz1, (s1+oacc[mt][nc][3])*rz1);
      *(float2*)(out + ((size_t)(bb*N_ + n0 + r  ))*E_ + c) = y0;
      *(float2*)(out + ((size_t)(bb*N_ + n0 + r+8))*E_ + c) = y1;
    }
  }
}

extern "C" void kernel_launch(void* const* d_in, const int* in_sizes, int n_in,
                              void* d_out, int out_size){
  const float* x  = (const float*)d_in[0];
  const float* Wq = (const float*)d_in[1];
  const float* bq = (const float*)d_in[2];
  const float* Wk = (const float*)d_in[3];
  const float* bk = (const float*)d_in[4];
  const float* Wv = (const float*)d_in[5];
  const float* bv = (const float*)d_in[6];
  float* out = (float*)d_out;

  cudaFuncSetAttribute(k_qkv,  cudaFuncAttributeMaxDynamicSharedMemorySize, C_SMEM);
  cudaFuncSetAttribute(k_attn, cudaFuncAttributeMaxDynamicSharedMemorySize, A_SMEM);

  // resolve device-global addresses for conversion kernels
  __nv_bfloat16 *xb_p, *wq_p, *wk_p, *wv_p;
  cudaGetSymbolAddress((void**)&xb_p, g_xb);
  cudaGetSymbolAddress((void**)&wq_p, g_Wqb);
  cudaGetSymbolAddress((void**)&wk_p, g_Wkb);
  cudaGetSymbolAddress((void**)&wv_p, g_Wvb);

  // fp32 -> bf16 staging
  k_cvt<<<(M_TOTAL*D_/4 + 255)/256, 256>>>((const float4*)x,  (__nv_bfloat162*)xb_p, M_TOTAL*D_/4);
  k_cvt<<<(D_*E_/4 + 255)/256, 256>>>((const float4*)Wq, (__nv_bfloat162*)wq_p, D_*E_/4);
  k_cvt<<<(D_*E_/4 + 255)/256, 256>>>((const float4*)Wk, (__nv_bfloat162*)wk_p, D_*E_/4);
  k_cvt<<<(D_*E_/4 + 255)/256, 256>>>((const float4*)Wv, (__nv_bfloat162*)wv_p, D_*E_/4);

  // exact fp32 path for S = sum_m v_m
  k_rowsum<<<dim3(8, B_, 8), 256>>>(x);
  k_sproj<<<B_, 256>>>(Wv, bv);

  // bf16 QKV projection
  k_qkv<<<dim3(M_TOTAL/C_BM, E_/C_BN, 3), 256, C_SMEM>>>(bq, bk, bv);

  // bf16 flash attention
  k_attn<<<dim3(N_/A_BM, B_), 256, A_SMEM>>>(out);
}

// round 5
// speedup vs baseline: 2.0637x; 1.0890x over previous
#include <cuda_runtime.h>
#include <cuda_bf16.h>
#include <cstdint>

#define B_ 8
#define N_ 2048
#define D_ 2048
#define E_ 256
#define M_TOTAL (B_*N_)   // 16384

// ---------------- scratch (device globals; no allocation allowed) ----------------
__device__ __nv_bfloat16 g_xb[M_TOTAL*D_];     // x in bf16 [M][D]
__device__ __nv_bfloat16 g_Wqb[D_*E_];         // W in bf16 [D][E]
__device__ __nv_bfloat16 g_Wkb[D_*E_];
__device__ __nv_bfloat16 g_Wvb[D_*E_];
__device__ __nv_bfloat16 g_Q[M_TOTAL*E_];
__device__ __nv_bfloat16 g_K[M_TOTAL*E_];
__device__ __nv_bfloat16 g_V[M_TOTAL*E_];
__device__ float g_xpart[16*B_*D_];            // partial column sums of x
__device__ float g_S[B_*E_];                   // exact fp32 sum_m v_m per batch

static __device__ __forceinline__ unsigned smem_u32(const void* p){
  return (unsigned)__cvta_generic_to_shared(p);
}
static __device__ __forceinline__ void cp16(unsigned dst, const void* src){
  asm volatile("cp.async.cg.shared.global [%0], [%1], 16;\n" :: "r"(dst), "l"(src));
}
static __device__ __forceinline__ void cp_commit(){
  asm volatile("cp.async.commit_group;\n");
}
template<int N> static __device__ __forceinline__ void cp_wait(){
  asm volatile("cp.async.wait_group %0;\n" :: "n"(N));
}
static __device__ __forceinline__ void ldsm_x4(unsigned* r, unsigned addr){
  asm volatile("ldmatrix.sync.aligned.m8n8.x4.shared.b16 {%0,%1,%2,%3}, [%4];\n"
    : "=r"(r[0]),"=r"(r[1]),"=r"(r[2]),"=r"(r[3]) : "r"(addr));
}
static __device__ __forceinline__ void ldsm_x4_t(unsigned* r, unsigned addr){
  asm volatile("ldmatrix.sync.aligned.m8n8.x4.trans.shared.b16 {%0,%1,%2,%3}, [%4];\n"
    : "=r"(r[0]),"=r"(r[1]),"=r"(r[2]),"=r"(r[3]) : "r"(addr));
}
static __device__ __forceinline__ void mma_bf16(float* c, const unsigned* a, unsigned b0, unsigned b1){
  asm volatile("mma.sync.aligned.m16n8k16.row.col.f32.bf16.bf16.f32 "
    "{%0,%1,%2,%3}, {%4,%5,%6,%7}, {%8,%9}, {%0,%1,%2,%3};\n"
    : "+f"(c[0]), "+f"(c[1]), "+f"(c[2]), "+f"(c[3])
    : "r"(a[0]), "r"(a[1]), "r"(a[2]), "r"(a[3]), "r"(b0), "r"(b1));
}

// ---------------- Kernel 1: fused x fp32->bf16 + per-batch partial column sums ----------------
__global__ void k_xcvt(const float* __restrict__ x){
  int b = blockIdx.y, ns = blockIdx.z;
  int d = blockIdx.x*1024 + threadIdx.x*4;
  const float4* src = (const float4*)(x + (size_t)b*N_*D_ + (size_t)ns*128*D_ + d);
  __nv_bfloat162* dst = (__nv_bfloat162*)(g_xb + (size_t)b*N_*D_ + (size_t)ns*128*D_ + d);
  float s0=0.f,s1=0.f,s2=0.f,s3=0.f;
  for(int n=0;n<128;n++){
    float4 v = src[(size_t)n*(D_/4)];
    s0+=v.x; s1+=v.y; s2+=v.z; s3+=v.w;
    dst[(size_t)n*(D_/2)  ] = __floats2bfloat162_rn(v.x,v.y);
    dst[(size_t)n*(D_/2)+1] = __floats2bfloat162_rn(v.z,v.w);
  }
  *(float4*)(g_xpart + ((size_t)(ns*B_+b))*D_ + d) = make_float4(s0,s1,s2,s3);
}

// ---------------- Kernel 2: W fp32 -> bf16 (no transpose; row-major [D][E]) ----------------
__global__ void k_cvt(const float4* __restrict__ src, __nv_bfloat162* __restrict__ dst, int n4){
  int i = blockIdx.x*blockDim.x + threadIdx.x;
  if(i < n4){
    float4 v = src[i];
    dst[2*i  ] = __floats2bfloat162_rn(v.x, v.y);
    dst[2*i+1] = __floats2bfloat162_rn(v.z, v.w);
  }
}

// ---------------- Kernel 3: S[b] = xsum[b] @ Wv + 2048*bv (exact fp32) ----------------
__global__ void k_sproj(const float* __restrict__ Wv, const float* __restrict__ bv){
  __shared__ float xs[D_];
  int b = blockIdx.x, e = threadIdx.x;
  for(int i=e;i<D_;i+=256){
    float s = 0.f;
    #pragma unroll
    for(int ns=0;ns<16;ns++) s += g_xpart[(size_t)(ns*B_ + b)*D_ + i];
    xs[i] = s;
  }
  __syncthreads();
  float a0=0.f,a1=0.f,a2=0.f,a3=0.f;
  for(int d=0;d<D_;d+=4){
    a0 += xs[d  ]*Wv[(size_t)(d  )*E_+e];
    a1 += xs[d+1]*Wv[(size_t)(d+1)*E_+e];
    a2 += xs[d+2]*Wv[(size_t)(d+2)*E_+e];
    a3 += xs[d+3]*Wv[(size_t)(d+3)*E_+e];
  }
  g_S[b*E_+e] = (a0+a1)+(a2+a3) + 2048.0f*bv[e];
}

// ---------------- Kernel 4: QKV = xb @ W + b  (bf16 HMMA, CTA 128x256, warp 64x64) ----------------
// smem map: [0..1024) bias fp32 (256 used), A stages at 1024 (2 x 128*80B),
//           B stages at 1024+20480 (2 x 32*528B)
#define QK_A_OFF 1024
#define QK_B_OFF (1024 + 2*128*80)
#define QK_SMEM (QK_B_OFF + 2*32*528)

__global__ __launch_bounds__(256) void k_qkv(
    const float* __restrict__ bq, const float* __restrict__ bk, const float* __restrict__ bv)
{
  extern __shared__ char qs[];
  unsigned sb = smem_u32(qs);
  float* biass = (float*)qs;

  int z = blockIdx.z;
  const __nv_bfloat16* W = z==0 ? g_Wqb : (z==1 ? g_Wkb : g_Wvb);
  const float* bias = z==0 ? bq : (z==1 ? bk : bv);
  __nv_bfloat16* outp = z==0 ? g_Q : (z==1 ? g_K : g_V);

  int m0 = blockIdx.x*128;
  int tid = threadIdx.x;
  int w = tid>>5, lane = tid&31, g = lane>>2, tg = lane&3;
  int wm = w>>2, wn = w&3;   // warp tile 64(m) x 64(n)

  biass[tid] = bias[tid];

  float acc[4][8][4];
  #pragma unroll
  for(int mt=0;mt<4;mt++)
    #pragma unroll
    for(int nc=0;nc<8;nc++)
      #pragma unroll
      for(int i=0;i<4;i++) acc[mt][nc][i]=0.f;

  unsigned a_base = sb + QK_A_OFF;
  unsigned b_base = sb + QK_B_OFF;
  const __nv_bfloat16* xsrc = g_xb + (size_t)m0*D_;

  // A stage load: 128 rows x 32 cols bf16 = 64B/row (80B padded) -> 512 cp16 (2/thread)
  // B stage load: 32 rows x 256 cols bf16 = 512B/row (528B padded) -> 1024 cp16 (4/thread)
  // prologue: stage 0
  {
    #pragma unroll
    for(int j=0;j<2;j++){
      int idx = tid + 256*j; int row = idx>>2, c16 = idx&3;
      cp16(a_base + (unsigned)(row*80 + c16*16), xsrc + (size_t)row*D_ + c16*8);
    }
    #pragma unroll
    for(int j=0;j<4;j++){
      int idx = tid + 256*j; int row = idx>>5, c16 = idx&31;
      cp16(b_base + (unsigned)(row*528 + c16*16), W + (size_t)row*E_ + c16*8);
    }
    cp_commit();
  }

  const int KT = D_/32;  // 64
  for(int kt=0; kt<KT; kt++){
    int cur = kt&1;
    if(kt+1 < KT){
      int nxt = cur^1;
      unsigned da = a_base + (unsigned)(nxt*128*80);
      unsigned db = b_base + (unsigned)(nxt*32*528);
      #pragma unroll
      for(int j=0;j<2;j++){
        int idx = tid + 256*j; int row = idx>>2, c16 = idx&3;
        cp16(da + (unsigned)(row*80 + c16*16), xsrc + (size_t)row*D_ + (kt+1)*32 + c16*8);
      }
      #pragma unroll
      for(int j=0;j<4;j++){
        int idx = tid + 256*j; int row = idx>>5, c16 = idx&31;
        cp16(db + (unsigned)(row*528 + c16*16), W + ((size_t)((kt+1)*32+row))*E_ + c16*8);
      }
      cp_commit();
      cp_wait<1>();
    } else {
      cp_wait<0>();
    }
    __syncthreads();

    unsigned ac = a_base + (unsigned)(cur*128*80);
    unsigned bc = b_base + (unsigned)(cur*32*528);
    #pragma unroll
    for(int kc=0;kc<2;kc++){
      unsigned a[4][4];
      #pragma unroll
      for(int mt=0;mt<4;mt++){
        int row = wm*64 + mt*16 + (lane&15);
        int col = kc*16 + (lane>>4)*8;
        ldsm_x4(a[mt], ac + (unsigned)(row*80 + col*2));
      }
      #pragma unroll
      for(int nb=0;nb<4;nb++){
        unsigned r[4];
        int row = kc*16 + (lane&7) + ((lane>>3)&1)*8;
        int col = wn*64 + nb*16 + (lane>>4)*8;
        ldsm_x4_t(r, bc + (unsigned)(row*528 + col*2));
        #pragma unroll
        for(int mt=0;mt<4;mt++){
          mma_bf16(acc[mt][2*nb  ], a[mt], r[0], r[1]);
          mma_bf16(acc[mt][2*nb+1], a[mt], r[2], r[3]);
        }
      }
    }
    __syncthreads();
  }

  // epilogue: +bias, store bf16
  #pragma unroll
  for(int mt=0;mt<4;mt++){
    int r0 = m0 + wm*64 + mt*16 + g;
    #pragma unroll
    for(int nc=0;nc<8;nc++){
      int c = wn*64 + nc*8 + 2*tg;
      float b0 = biass[c], b1 = biass[c+1];
      *(__nv_bfloat162*)(outp + (size_t)r0*E_ + c) =
        __floats2bfloat162_rn(acc[mt][nc][0]+b0, acc[mt][nc][1]+b1);
      *(__nv_bfloat162*)(outp + (size_t)(r0+8)*E_ + c) =
        __floats2bfloat162_rn(acc[mt][nc][2]+b0, acc[mt][nc][3]+b1);
    }
  }
}

// ---------------- Kernel 5: flash attention, e = 1 + p decomposition, bf16 mma ----------------
#define A_BM 64
#define A_BN 64
#define QKST 264
#define PST  72
#define A_Q_OFF 0
#define A_K_OFF (64*QKST)
#define A_V_OFF (3*64*QKST)
#define A_P_OFF (5*64*QKST)
#define A_SMEM_BF (5*64*QKST + 64*PST)
#define A_SMEM (A_SMEM_BF*2 + (64+256)*4)

__global__ __launch_bounds__(256,1) void k_attn(float* __restrict__ out){
  extern __shared__ __nv_bfloat16 sma[];
  __nv_bfloat16* Qs = sma + A_Q_OFF;
  __nv_bfloat16* Ks = sma + A_K_OFF;
  __nv_bfloat16* Vs = sma + A_V_OFF;
  __nv_bfloat16* Ps = sma + A_P_OFF;
  float* Zs = (float*)(sma + A_SMEM_BF);
  float* Ss = Zs + 64;

  int bb = blockIdx.y;
  int n0 = blockIdx.x*A_BM;
  int tid = threadIdx.x;
  int w = tid>>5, lane = tid&31, g = lane>>2, tg = lane&3;
  int swm = w&3, swn = w>>2;
  int owm = w>>2, own = w&3;

  if(tid < 64) Zs[tid] = 0.0f;
  Ss[tid] = g_S[bb*E_ + tid];

  unsigned q_base = smem_u32(Qs);
  unsigned k_base = smem_u32(Ks);
  unsigned v_base = smem_u32(Vs);
  unsigned p_base = smem_u32(Ps);

  {
    const __nv_bfloat16* qsrc = g_Q + ((size_t)(bb*N_ + n0))*E_;
    const __nv_bfloat16* ksrc = g_K + ((size_t)bb*N_)*E_;
    const __nv_bfloat16* vsrc = g_V + ((size_t)bb*N_)*E_;
    #pragma unroll
    for(int j=0;j<8;j++){
      int idx = tid + 256*j; int row = idx>>5, c16 = idx&31;
      unsigned off = (unsigned)(row*528 + c16*16);
      size_t soff = (size_t)row*E_ + c16*8;
      cp16(q_base + off, qsrc + soff);
      cp16(k_base + off, ksrc + soff);
      cp16(v_base + off, vsrc + soff);
    }
    cp_commit();
  }

  float oacc[2][8][4];
  #pragma unroll
  for(int mt=0;mt<2;mt++)
    #pragma unroll
    for(int nc=0;nc<8;nc++)
      #pragma unroll
      for(int i=0;i<4;i++) oacc[mt][nc][i]=0.f;

  const int KB = N_/A_BN;
  for(int kb=0; kb<KB; kb++){
    int cur = kb&1;
    if(kb+1 < KB){
      int nxt = cur^1;
      unsigned dk = k_base + (unsigned)(nxt*64*QKST*2);
      unsigned dv = v_base + (unsigned)(nxt*64*QKST*2);
      const __nv_bfloat16* ksrc = g_K + ((size_t)(bb*N_ + (kb+1)*A_BN))*E_;
      const __nv_bfloat16* vsrc = g_V + ((size_t)(bb*N_ + (kb+1)*A_BN))*E_;
      #pragma unroll
      for(int j=0;j<8;j++){
        int idx = tid + 256*j; int row = idx>>5, c16 = idx&31;
        unsigned off = (unsigned)(row*528 + c16*16);
        size_t soff = (size_t)row*E_ + c16*8;
        cp16(dk + off, ksrc + soff);
        cp16(dv + off, vsrc + soff);
      }
      cp_commit();
      cp_wait<1>();
    } else {
      cp_wait<0>();
    }
    __syncthreads();

    unsigned kc_base = k_base + (unsigned)(cur*64*QKST*2);
    unsigned vc_base = v_base + (unsigned)(cur*64*QKST*2);

    float sc[4][4];
    #pragma unroll
    for(int nc=0;nc<4;nc++)
      #pragma unroll
      for(int i=0;i<4;i++) sc[nc][i]=0.f;

    #pragma unroll
    for(int kc=0;kc<16;kc++){
      unsigned a[4];
      {
        int row = swm*16 + (lane&15);
        int col = kc*16 + (lane>>4)*8;
        ldsm_x4(a, q_base + (unsigned)(row*528 + col*2));
      }
      #pragma unroll
      for(int nb=0;nb<2;nb++){
        unsigned r[4];
        int row = swn*32 + nb*16 + (lane&15);
        int col = kc*16 + (lane>>4)*8;
        ldsm_x4(r, kc_base + (unsigned)(row*528 + col*2));
        mma_bf16(sc[2*nb  ], a, r[0], r[2]);
        mma_bf16(sc[2*nb+1], a, r[1], r[3]);
      }
    }

    float zlo=0.f, zhi=0.f;
    #pragma unroll
    for(int nc=0;nc<4;nc++){
      #pragma unroll
      for(int i=0;i<4;i++){
        float s = sc[nc][i];
        float sig = __fdividef(1.0f, 1.0f + __expf(-s));
        float gg = 0.0625f * sig;
        sc[nc][i] = gg*fmaf(gg, fmaf(gg, fmaf(gg, 0.041666668f, 0.16666667f), 0.5f), 1.0f);
      }
      zlo += sc[nc][0]+sc[nc][1];
      zhi += sc[nc][2]+sc[nc][3];
    }
    zlo += __shfl_xor_sync(0xffffffffu, zlo, 1);
    zlo += __shfl_xor_sync(0xffffffffu, zlo, 2);
    zhi += __shfl_xor_sync(0xffffffffu, zhi, 1);
    zhi += __shfl_xor_sync(0xffffffffu, zhi, 2);
    if(tg==0){
      atomicAdd(&Zs[swm*16+g],   zlo);
      atomicAdd(&Zs[swm*16+g+8], zhi);
    }
    #pragma unroll
    for(int nc=0;nc<4;nc++){
      int c = swn*32 + nc*8 + 2*tg;
      *(__nv_bfloat162*)((char*)Ps + (swm*16+g  )*144 + c*2) =
        __floats2bfloat162_rn(sc[nc][0], sc[nc][1]);
      *(__nv_bfloat162*)((char*)Ps + (swm*16+g+8)*144 + c*2) =
        __floats2bfloat162_rn(sc[nc][2], sc[nc][3]);
    }
    __syncthreads();

    #pragma unroll
    for(int kc=0;kc<4;kc++){
      unsigned a[2][4];
      #pragma unroll
      for(int mt=0;mt<2;mt++){
        int row = owm*32 + mt*16 + (lane&15);
        int col = kc*16 + (lane>>4)*8;
        ldsm_x4(a[mt], p_base + (unsigned)(row*144 + col*2));
      }
      #pragma unroll
      for(int nb=0;nb<4;nb++){
        unsigned r[4];
        int row = kc*16 + (lane&7) + ((lane>>3)&1)*8;
        int col = own*64 + nb*16 + (lane>>4)*8;
        ldsm_x4_t(r, vc_base + (unsigned)(row*528 + col*2));
        #pragma unroll
        for(int mt=0;mt<2;mt++){
          mma_bf16(oacc[mt][2*nb  ], a[mt], r[0], r[1]);
          mma_bf16(oacc[mt][2*nb+1], a[mt], r[2], r[3]);
        }
      }
    }
    __syncthreads();
  }

  #pragma unroll
  for(int mt=0;mt<2;mt++){
    int r = owm*32 + mt*16 + g;
    float rz0 = __fdividef(1.0f, 2048.0f + Zs[r]);
    float rz1 = __fdividef(1.0f, 2048.0f + Zs[r+8]);
    #pragma unroll
    for(int nc=0;nc<8;nc++){
      int c = own*64 + nc*8 + 2*tg;
      float s0 = Ss[c], s1 = Ss[c+1];
      float2 y0 = make_float2((s0+oacc[mt][nc][0])*rz0, (s1+oacc[mt][nc][1])*rz0);
      float2 y1 = make_float2((s0+oacc[mt][nc][2])*rz1, (s1+oacc[mt][nc][3])*rz1);
      *(float2*)(out + ((size_t)(bb*N_ + n0 + r  ))*E_ + c) = y0;
      *(float2*)(out + ((size_t)(bb*N_ + n0 + r+8))*E_ + c) = y1;
    }
  }
}

extern "C" void kernel_launch(void* const* d_in, const int* in_sizes, int n_in,
                              void* d_out, int out_size){
  const float* x  = (const float*)d_in[0];
  const float* Wq = (const float*)d_in[1];
  const float* bq = (const float*)d_in[2];
  const float* Wk = (const float*)d_in[3];
  const float* bk = (const float*)d_in[4];
  const float* Wv = (const float*)d_in[5];
  const float* bv = (const float*)d_in[6];
  float* out = (float*)d_out;

  cudaFuncSetAttribute(k_qkv,  cudaFuncAttributeMaxDynamicSharedMemorySize, QK_SMEM);
  cudaFuncSetAttribute(k_attn, cudaFuncAttributeMaxDynamicSharedMemorySize, A_SMEM);

  __nv_bfloat16 *wq_p, *wk_p, *wv_p;
  cudaGetSymbolAddress((void**)&wq_p, g_Wqb);
  cudaGetSymbolAddress((void**)&wk_p, g_Wkb);
  cudaGetSymbolAddress((void**)&wv_p, g_Wvb);

  // staging: x -> bf16 fused with partial column sums; W -> bf16
  k_xcvt<<<dim3(2, B_, 16), 256>>>(x);
  k_cvt<<<(D_*E_/4 + 255)/256, 256>>>((const float4*)Wq, (__nv_bfloat162*)wq_p, D_*E_/4);
  k_cvt<<<(D_*E_/4 + 255)/256, 256>>>((const float4*)Wk, (__nv_bfloat162*)wk_p, D_*E_/4);
  k_cvt<<<(D_*E_/4 + 255)/256, 256>>>((const float4*)Wv, (__nv_bfloat162*)wv_p, D_*E_/4);

  // exact fp32 S = sum_m v_m
  k_sproj<<<B_, 256>>>(Wv, bv);

  // bf16 QKV projection (HMMA, 64x64 warp tiles)
  k_qkv<<<dim3(M_TOTAL/128, 1, 3), 256, QK_SMEM>>>(bq, bk, bv);

  // bf16 flash attention (HMMA)
  k_attn<<<dim3(N_/A_BM, B_), 256, A_SMEM>>>(out);
}

// round 6
// speedup vs baseline: 2.5463x; 1.2338x over previous
#include <cuda_runtime.h>
#include <cuda_bf16.h>
#include <cstdint>

#define B_ 8
#define N_ 2048
#define D_ 2048
#define E_ 256
#define M_TOTAL (B_*N_)   // 16384

// ---------------- scratch (device globals; no allocation allowed) ----------------
__device__ __nv_bfloat16 g_xb[M_TOTAL*D_];     // x in bf16 [M][D]
__device__ __nv_bfloat16 g_Wqb[D_*E_];         // W in bf16 [D][E]
__device__ __nv_bfloat16 g_Wkb[D_*E_];
__device__ __nv_bfloat16 g_Wvb[D_*E_];
__device__ __nv_bfloat16 g_Q[M_TOTAL*E_];
__device__ __nv_bfloat16 g_K[M_TOTAL*E_];
__device__ __nv_bfloat16 g_V[M_TOTAL*E_];
__device__ float g_xpart[16*B_*D_];            // partial column sums of x
__device__ float g_spart[8*B_*E_];             // partial S projections
__device__ float g_S[B_*E_];                   // exact fp32 sum_m v_m per batch

static __device__ __forceinline__ unsigned smem_u32(const void* p){
  return (unsigned)__cvta_generic_to_shared(p);
}
static __device__ __forceinline__ void cp16(unsigned dst, const void* src){
  asm volatile("cp.async.cg.shared.global [%0], [%1], 16;\n" :: "r"(dst), "l"(src));
}
static __device__ __forceinline__ void cp_commit(){
  asm volatile("cp.async.commit_group;\n");
}
template<int N> static __device__ __forceinline__ void cp_wait(){
  asm volatile("cp.async.wait_group %0;\n" :: "n"(N));
}
static __device__ __forceinline__ void ldsm_x4(unsigned* r, unsigned addr){
  asm volatile("ldmatrix.sync.aligned.m8n8.x4.shared.b16 {%0,%1,%2,%3}, [%4];\n"
    : "=r"(r[0]),"=r"(r[1]),"=r"(r[2]),"=r"(r[3]) : "r"(addr));
}
static __device__ __forceinline__ void ldsm_x4_t(unsigned* r, unsigned addr){
  asm volatile("ldmatrix.sync.aligned.m8n8.x4.trans.shared.b16 {%0,%1,%2,%3}, [%4];\n"
    : "=r"(r[0]),"=r"(r[1]),"=r"(r[2]),"=r"(r[3]) : "r"(addr));
}
static __device__ __forceinline__ void mma_bf16(float* c, const unsigned* a, unsigned b0, unsigned b1){
  asm volatile("mma.sync.aligned.m16n8k16.row.col.f32.bf16.bf16.f32 "
    "{%0,%1,%2,%3}, {%4,%5,%6,%7}, {%8,%9}, {%0,%1,%2,%3};\n"
    : "+f"(c[0]), "+f"(c[1]), "+f"(c[2]), "+f"(c[3])
    : "r"(a[0]), "r"(a[1]), "r"(a[2]), "r"(a[3]), "r"(b0), "r"(b1));
}

// ---------------- Kernel 1: fused x fp32->bf16 + per-batch partial column sums ----------------
__global__ void k_xcvt(const float* __restrict__ x){
  int b = blockIdx.y, ns = blockIdx.z;
  int d = blockIdx.x*1024 + threadIdx.x*4;
  const float4* src = (const float4*)(x + (size_t)b*N_*D_ + (size_t)ns*128*D_ + d);
  __nv_bfloat162* dst = (__nv_bfloat162*)(g_xb + (size_t)b*N_*D_ + (size_t)ns*128*D_ + d);
  float s0=0.f,s1=0.f,s2=0.f,s3=0.f;
  for(int n=0;n<128;n++){
    float4 v = src[(size_t)n*(D_/4)];
    s0+=v.x; s1+=v.y; s2+=v.z; s3+=v.w;
    dst[(size_t)n*(D_/2)  ] = __floats2bfloat162_rn(v.x,v.y);
    dst[(size_t)n*(D_/2)+1] = __floats2bfloat162_rn(v.z,v.w);
  }
  *(float4*)(g_xpart + ((size_t)(ns*B_+b))*D_ + d) = make_float4(s0,s1,s2,s3);
}

// ---------------- Kernel 2: W fp32 -> bf16 (all three in one launch) ----------------
__global__ void k_wcvt(const float4* __restrict__ Wq, const float4* __restrict__ Wk,
                       const float4* __restrict__ Wv){
  int z = blockIdx.y;
  const float4* src = z==0 ? Wq : (z==1 ? Wk : Wv);
  __nv_bfloat162* dst = (__nv_bfloat162*)(z==0 ? g_Wqb : (z==1 ? g_Wkb : g_Wvb));
  int i = blockIdx.x*256 + threadIdx.x;
  float4 v = src[i];
  dst[2*i  ] = __floats2bfloat162_rn(v.x, v.y);
  dst[2*i+1] = __floats2bfloat162_rn(v.z, v.w);
}

// ---------------- Kernel 3a/3b: S[b] = xsum[b] @ Wv + 2048*bv (exact fp32, split) ----------------
__global__ void k_sproj1(const float* __restrict__ Wv){
  __shared__ float xs[256];
  int b = blockIdx.x, ds = blockIdx.y, e = threadIdx.x;
  {
    float s = 0.f;
    #pragma unroll
    for(int ns=0;ns<16;ns++) s += g_xpart[(size_t)(ns*B_ + b)*D_ + ds*256 + e];
    xs[e] = s;
  }
  __syncthreads();
  const float* Wp = Wv + (size_t)ds*256*E_ + e;
  float a0=0.f,a1=0.f,a2=0.f,a3=0.f;
  for(int d=0;d<256;d+=4){
    a0 += xs[d  ]*Wp[(size_t)(d  )*E_];
    a1 += xs[d+1]*Wp[(size_t)(d+1)*E_];
    a2 += xs[d+2]*Wp[(size_t)(d+2)*E_];
    a3 += xs[d+3]*Wp[(size_t)(d+3)*E_];
  }
  g_spart[(ds*B_+b)*E_ + e] = (a0+a1)+(a2+a3);
}
__global__ void k_sproj2(const float* __restrict__ bv){
  int b = blockIdx.x, e = threadIdx.x;
  float s = 2048.0f*bv[e];
  #pragma unroll
  for(int ds=0;ds<8;ds++) s += g_spart[(ds*B_+b)*E_ + e];
  g_S[b*E_+e] = s;
}

// ---------------- Kernel 4: QKV = xb @ W + b  (bf16 HMMA, CTA 128x256, warp 64x64) ----------------
#define QK_A_OFF 1024
#define QK_B_OFF (1024 + 2*128*80)
#define QK_SMEM (QK_B_OFF + 2*32*528)

__global__ __launch_bounds__(256) void k_qkv(
    const float* __restrict__ bq, const float* __restrict__ bk, const float* __restrict__ bv)
{
  extern __shared__ char qs[];
  unsigned sb = smem_u32(qs);
  float* biass = (float*)qs;

  int z = blockIdx.z;
  const __nv_bfloat16* W = z==0 ? g_Wqb : (z==1 ? g_Wkb : g_Wvb);
  const float* bias = z==0 ? bq : (z==1 ? bk : bv);
  __nv_bfloat16* outp = z==0 ? g_Q : (z==1 ? g_K : g_V);

  int m0 = blockIdx.x*128;
  int tid = threadIdx.x;
  int w = tid>>5, lane = tid&31, g = lane>>2, tg = lane&3;
  int wm = w>>2, wn = w&3;   // warp tile 64(m) x 64(n)

  biass[tid] = bias[tid];

  float acc[4][8][4];
  #pragma unroll
  for(int mt=0;mt<4;mt++)
    #pragma unroll
    for(int nc=0;nc<8;nc++)
      #pragma unroll
      for(int i=0;i<4;i++) acc[mt][nc][i]=0.f;

  unsigned a_base = sb + QK_A_OFF;
  unsigned b_base = sb + QK_B_OFF;
  const __nv_bfloat16* xsrc = g_xb + (size_t)m0*D_;

  {
    #pragma unroll
    for(int j=0;j<2;j++){
      int idx = tid + 256*j; int row = idx>>2, c16 = idx&3;
      cp16(a_base + (unsigned)(row*80 + c16*16), xsrc + (size_t)row*D_ + c16*8);
    }
    #pragma unroll
    for(int j=0;j<4;j++){
      int idx = tid + 256*j; int row = idx>>5, c16 = idx&31;
      cp16(b_base + (unsigned)(row*528 + c16*16), W + (size_t)row*E_ + c16*8);
    }
    cp_commit();
  }

  const int KT = D_/32;  // 64
  for(int kt=0; kt<KT; kt++){
    int cur = kt&1;
    if(kt+1 < KT){
      int nxt = cur^1;
      unsigned da = a_base + (unsigned)(nxt*128*80);
      unsigned db = b_base + (unsigned)(nxt*32*528);
      #pragma unroll
      for(int j=0;j<2;j++){
        int idx = tid + 256*j; int row = idx>>2, c16 = idx&3;
        cp16(da + (unsigned)(row*80 + c16*16), xsrc + (size_t)row*D_ + (kt+1)*32 + c16*8);
      }
      #pragma unroll
      for(int j=0;j<4;j++){
        int idx = tid + 256*j; int row = idx>>5, c16 = idx&31;
        cp16(db + (unsigned)(row*528 + c16*16), W + ((size_t)((kt+1)*32+row))*E_ + c16*8);
      }
      cp_commit();
      cp_wait<1>();
    } else {
      cp_wait<0>();
    }
    __syncthreads();

    unsigned ac = a_base + (unsigned)(cur*128*80);
    unsigned bc = b_base + (unsigned)(cur*32*528);
    #pragma unroll
    for(int kc=0;kc<2;kc++){
      unsigned a[4][4];
      #pragma unroll
      for(int mt=0;mt<4;mt++){
        int row = wm*64 + mt*16 + (lane&15);
        int col = kc*16 + (lane>>4)*8;
        ldsm_x4(a[mt], ac + (unsigned)(row*80 + col*2));
      }
      #pragma unroll
      for(int nb=0;nb<4;nb++){
        unsigned r[4];
        int row = kc*16 + (lane&7) + ((lane>>3)&1)*8;
        int col = wn*64 + nb*16 + (lane>>4)*8;
        ldsm_x4_t(r, bc + (unsigned)(row*528 + col*2));
        #pragma unroll
        for(int mt=0;mt<4;mt++){
          mma_bf16(acc[mt][2*nb  ], a[mt], r[0], r[1]);
          mma_bf16(acc[mt][2*nb+1], a[mt], r[2], r[3]);
        }
      }
    }
    __syncthreads();
  }

  #pragma unroll
  for(int mt=0;mt<4;mt++){
    int r0 = m0 + wm*64 + mt*16 + g;
    #pragma unroll
    for(int nc=0;nc<8;nc++){
      int c = wn*64 + nc*8 + 2*tg;
      float b0 = biass[c], b1 = biass[c+1];
      *(__nv_bfloat162*)(outp + (size_t)r0*E_ + c) =
        __floats2bfloat162_rn(acc[mt][nc][0]+b0, acc[mt][nc][1]+b1);
      *(__nv_bfloat162*)(outp + (size_t)(r0+8)*E_ + c) =
        __floats2bfloat162_rn(acc[mt][nc][2]+b0, acc[mt][nc][3]+b1);
    }
  }
}

// ---------------- Kernel 5: flash attention, Q tile 128 rows, e = 1 + p decomposition ----------------
#define A_BM 128
#define A_BN 64
#define QKST 264   // 528B rows for Q/K/V tiles
#define PST  72    // 144B rows for P
#define AQ_OFF 0
#define AK_OFF (128*QKST)
#define AV_OFF (AK_OFF + 2*64*QKST)
#define AP_OFF (AV_OFF + 2*64*QKST)
#define A_BF_TOT (AP_OFF + 128*PST)
#define A_SMEM (A_BF_TOT*2 + (128+256)*4)

__global__ __launch_bounds__(256,1) void k_attn(float* __restrict__ out){
  extern __shared__ __nv_bfloat16 sma[];
  float* Zs = (float*)(sma + A_BF_TOT);   // [128]
  float* Ss = Zs + 128;                   // [256]

  int bb = blockIdx.y;
  int n0 = blockIdx.x*A_BM;
  int tid = threadIdx.x;
  int w = tid>>5, lane = tid&31, g = lane>>2, tg = lane&3;
  int swm = w&3, swn = w>>2;   // scores: 32x32 warp tiles (4m x 2n); PV: 32x128 (same mapping)

  if(tid < 128) Zs[tid] = 0.0f;
  Ss[tid] = g_S[bb*E_ + tid];

  unsigned q_base = smem_u32(sma + AQ_OFF);
  unsigned k_base = smem_u32(sma + AK_OFF);
  unsigned v_base = smem_u32(sma + AV_OFF);
  unsigned p_base = smem_u32(sma + AP_OFF);

  // prologue: Q tile (128 rows) + KV block 0
  {
    const __nv_bfloat16* qsrc = g_Q + ((size_t)(bb*N_ + n0))*E_;
    const __nv_bfloat16* ksrc = g_K + ((size_t)bb*N_)*E_;
    const __nv_bfloat16* vsrc = g_V + ((size_t)bb*N_)*E_;
    #pragma unroll
    for(int j=0;j<16;j++){
      int idx = tid + 256*j; int row = idx>>5, c16 = idx&31;
      cp16(q_base + (unsigned)(row*528 + c16*16), qsrc + (size_t)row*E_ + c16*8);
    }
    #pragma unroll
    for(int j=0;j<8;j++){
      int idx = tid + 256*j; int row = idx>>5, c16 = idx&31;
      unsigned off = (unsigned)(row*528 + c16*16);
      size_t soff = (size_t)row*E_ + c16*8;
      cp16(k_base + off, ksrc + soff);
      cp16(v_base + off, vsrc + soff);
    }
    cp_commit();
  }

  float oacc[2][16][4];
  #pragma unroll
  for(int mt=0;mt<2;mt++)
    #pragma unroll
    for(int nc=0;nc<16;nc++)
      #pragma unroll
      for(int i=0;i<4;i++) oacc[mt][nc][i]=0.f;

  const int KB = N_/A_BN;  // 32
  for(int kb=0; kb<KB; kb++){
    int cur = kb&1;
    if(kb+1 < KB){
      int nxt = cur^1;
      unsigned dk = k_base + (unsigned)(nxt*64*QKST*2);
      unsigned dv = v_base + (unsigned)(nxt*64*QKST*2);
      const __nv_bfloat16* ksrc = g_K + ((size_t)(bb*N_ + (kb+1)*A_BN))*E_;
      const __nv_bfloat16* vsrc = g_V + ((size_t)(bb*N_ + (kb+1)*A_BN))*E_;
      #pragma unroll
      for(int j=0;j<8;j++){
        int idx = tid + 256*j; int row = idx>>5, c16 = idx&31;
        unsigned off = (unsigned)(row*528 + c16*16);
        size_t soff = (size_t)row*E_ + c16*8;
        cp16(dk + off, ksrc + soff);
        cp16(dv + off, vsrc + soff);
      }
      cp_commit();
      cp_wait<1>();
    } else {
      cp_wait<0>();
    }
    __syncthreads();

    unsigned kc_base = k_base + (unsigned)(cur*64*QKST*2);
    unsigned vc_base = v_base + (unsigned)(cur*64*QKST*2);

    // ---- scores: 128x64, warp tile 32x32 ----
    float sc[2][4][4];
    #pragma unroll
    for(int mt=0;mt<2;mt++)
      #pragma unroll
      for(int nc=0;nc<4;nc++)
        #pragma unroll
        for(int i=0;i<4;i++) sc[mt][nc][i]=0.f;

    #pragma unroll
    for(int kc=0;kc<16;kc++){
      unsigned a[2][4];
      #pragma unroll
      for(int mt=0;mt<2;mt++){
        int row = swm*32 + mt*16 + (lane&15);
        int col = kc*16 + (lane>>4)*8;
        ldsm_x4(a[mt], q_base + (unsigned)(row*528 + col*2));
      }
      #pragma unroll
      for(int nb=0;nb<2;nb++){
        unsigned r[4];
        int row = swn*32 + nb*16 + (lane&15);
        int col = kc*16 + (lane>>4)*8;
        ldsm_x4(r, kc_base + (unsigned)(row*528 + col*2));
        #pragma unroll
        for(int mt=0;mt<2;mt++){
          mma_bf16(sc[mt][2*nb  ], a[mt], r[0], r[2]);
          mma_bf16(sc[mt][2*nb+1], a[mt], r[1], r[3]);
        }
      }
    }

    // ---- p = expm1(sigmoid(s)/16); Z row sums; store P bf16 ----
    #pragma unroll
    for(int mt=0;mt<2;mt++){
      float zlo=0.f, zhi=0.f;
      #pragma unroll
      for(int nc=0;nc<4;nc++){
        #pragma unroll
        for(int i=0;i<4;i++){
          float s = sc[mt][nc][i];
          float sig = __fdividef(1.0f, 1.0f + __expf(-s));
          float gg = 0.0625f * sig;
          sc[mt][nc][i] = gg*fmaf(gg, fmaf(gg, fmaf(gg, 0.041666668f, 0.16666667f), 0.5f), 1.0f);
        }
        zlo += sc[mt][nc][0]+sc[mt][nc][1];
        zhi += sc[mt][nc][2]+sc[mt][nc][3];
      }
      zlo += __shfl_xor_sync(0xffffffffu, zlo, 1);
      zlo += __shfl_xor_sync(0xffffffffu, zlo, 2);
      zhi += __shfl_xor_sync(0xffffffffu, zhi, 1);
      zhi += __shfl_xor_sync(0xffffffffu, zhi, 2);
      if(tg==0){
        atomicAdd(&Zs[swm*32+mt*16+g],   zlo);
        atomicAdd(&Zs[swm*32+mt*16+g+8], zhi);
      }
      #pragma unroll
      for(int nc=0;nc<4;nc++){
        int c = swn*32 + nc*8 + 2*tg;
        *(__nv_bfloat162*)((char*)sma + AP_OFF*2 + (swm*32+mt*16+g  )*144 + c*2) =
          __floats2bfloat162_rn(sc[mt][nc][0], sc[mt][nc][1]);
        *(__nv_bfloat162*)((char*)sma + AP_OFF*2 + (swm*32+mt*16+g+8)*144 + c*2) =
          __floats2bfloat162_rn(sc[mt][nc][2], sc[mt][nc][3]);
      }
    }
    __syncthreads();

    // ---- out += P @ V : P 128x64, V 64x256, warp tile 32x128 ----
    #pragma unroll
    for(int kc=0;kc<4;kc++){
      unsigned pa[2][4];
      #pragma unroll
      for(int mt=0;mt<2;mt++){
        int row = swm*32 + mt*16 + (lane&15);
        int col = kc*16 + (lane>>4)*8;
        ldsm_x4(pa[mt], p_base + (unsigned)(row*144 + col*2));
      }
      #pragma unroll
      for(int nb=0;nb<8;nb++){
        unsigned r[4];
        int row = kc*16 + (lane&7) + ((lane>>3)&1)*8;
        int col = swn*128 + nb*16 + (lane>>4)*8;
        ldsm_x4_t(r, vc_base + (unsigned)(row*528 + col*2));
        #pragma unroll
        for(int mt=0;mt<2;mt++){
          mma_bf16(oacc[mt][2*nb  ], pa[mt], r[0], r[1]);
          mma_bf16(oacc[mt][2*nb+1], pa[mt], r[2], r[3]);
        }
      }
    }
    __syncthreads();
  }

  // epilogue: out = (S + acc) / (2048 + Z)
  #pragma unroll
  for(int mt=0;mt<2;mt++){
    int r = swm*32 + mt*16 + g;
    float rz0 = __fdividef(1.0f, 2048.0f + Zs[r]);
    float rz1 = __fdividef(1.0f, 2048.0f + Zs[r+8]);
    #pragma unroll
    for(int nc=0;nc<16;nc++){
      int c = swn*128 + nc*8 + 2*tg;
      float s0 = Ss[c], s1 = Ss[c+1];
      float2 y0 = make_float2((s0+oacc[mt][nc][0])*rz0, (s1+oacc[mt][nc][1])*rz0);
      float2 y1 = make_float2((s0+oacc[mt][nc][2])*rz1, (s1+oacc[mt][nc][3])*rz1);
      *(float2*)(out + ((size_t)(bb*N_ + n0 + r  ))*E_ + c) = y0;
      *(float2*)(out + ((size_t)(bb*N_ + n0 + r+8))*E_ + c) = y1;
    }
  }
}

extern "C" void kernel_launch(void* const* d_in, const int* in_sizes, int n_in,
                              void* d_out, int out_size){
  const float* x  = (const float*)d_in[0];
  const float* Wq = (const float*)d_in[1];
  const float* bq = (const float*)d_in[2];
  const float* Wk = (const float*)d_in[3];
  const float* bk = (const float*)d_in[4];
  const float* Wv = (const float*)d_in[5];
  const float* bv = (const float*)d_in[6];
  float* out = (float*)d_out;

  cudaFuncSetAttribute(k_qkv,  cudaFuncAttributeMaxDynamicSharedMemorySize, QK_SMEM);
  cudaFuncSetAttribute(k_attn, cudaFuncAttributeMaxDynamicSharedMemorySize, A_SMEM);

  // staging
  k_xcvt<<<dim3(2, B_, 16), 256>>>(x);
  k_wcvt<<<dim3(D_*E_/4/256, 3), 256>>>((const float4*)Wq, (const float4*)Wk, (const float4*)Wv);

  // exact fp32 S = sum_m v_m (split over 64 CTAs, two-stage deterministic)
  k_sproj1<<<dim3(B_, 8), 256>>>(Wv);
  k_sproj2<<<B_, 256>>>(bv);

  // bf16 QKV projection (HMMA, 64x64 warp tiles)
  k_qkv<<<dim3(M_TOTAL/128, 1, 3), 256, QK_SMEM>>>(bq, bk, bv);

  // bf16 flash attention (HMMA, 128-row Q tiles, single wave)
  k_attn<<<dim3(N_/A_BM, B_), 256, A_SMEM>>>(out);
}

// round 7
// speedup vs baseline: 2.6057x; 1.0233x over previous
#include <cuda_runtime.h>
#include <cuda_bf16.h>
#include <cstdint>

#define B_ 8
#define N_ 2048
#define D_ 2048
#define E_ 256
#define M_TOTAL (B_*N_)   // 16384

// ---------------- scratch (device globals; no allocation allowed) ----------------
__device__ __nv_bfloat16 g_xb[M_TOTAL*D_];     // x in bf16 [M][D]
__device__ __nv_bfloat16 g_Wqb[D_*E_];         // W in bf16 [D][E]
__device__ __nv_bfloat16 g_Wkb[D_*E_];
__device__ __nv_bfloat16 g_Wvb[D_*E_];
__device__ __nv_bfloat16 g_Q[M_TOTAL*E_];
__device__ __nv_bfloat16 g_K[M_TOTAL*E_];
__device__ __nv_bfloat16 g_V[M_TOTAL*E_];
__device__ float g_xpart[16*B_*D_];            // partial column sums of x
__device__ float g_spart[8*B_*E_];             // partial S projections
__device__ float g_S[B_*E_];                   // exact fp32 sum_m v_m per batch

static __device__ __forceinline__ unsigned smem_u32(const void* p){
  return (unsigned)__cvta_generic_to_shared(p);
}
static __device__ __forceinline__ void cp16(unsigned dst, const void* src){
  asm volatile("cp.async.cg.shared.global [%0], [%1], 16;\n" :: "r"(dst), "l"(src));
}
static __device__ __forceinline__ void cp_commit(){
  asm volatile("cp.async.commit_group;\n");
}
template<int N> static __device__ __forceinline__ void cp_wait(){
  asm volatile("cp.async.wait_group %0;\n" :: "n"(N));
}
static __device__ __forceinline__ void bar_pair(int id){
  asm volatile("bar.sync %0, 64;\n" :: "r"(id) : "memory");
}
static __device__ __forceinline__ void ldsm_x4(unsigned* r, unsigned addr){
  asm volatile("ldmatrix.sync.aligned.m8n8.x4.shared.b16 {%0,%1,%2,%3}, [%4];\n"
    : "=r"(r[0]),"=r"(r[1]),"=r"(r[2]),"=r"(r[3]) : "r"(addr));
}
static __device__ __forceinline__ void ldsm_x4_t(unsigned* r, unsigned addr){
  asm volatile("ldmatrix.sync.aligned.m8n8.x4.trans.shared.b16 {%0,%1,%2,%3}, [%4];\n"
    : "=r"(r[0]),"=r"(r[1]),"=r"(r[2]),"=r"(r[3]) : "r"(addr));
}
static __device__ __forceinline__ void mma_bf16(float* c, const unsigned* a, unsigned b0, unsigned b1){
  asm volatile("mma.sync.aligned.m16n8k16.row.col.f32.bf16.bf16.f32 "
    "{%0,%1,%2,%3}, {%4,%5,%6,%7}, {%8,%9}, {%0,%1,%2,%3};\n"
    : "+f"(c[0]), "+f"(c[1]), "+f"(c[2]), "+f"(c[3])
    : "r"(a[0]), "r"(a[1]), "r"(a[2]), "r"(a[3]), "r"(b0), "r"(b1));
}

// ---------------- Kernel 1: fused x fp32->bf16 + per-batch partial column sums ----------------
__global__ void k_xcvt(const float* __restrict__ x){
  int b = blockIdx.y, ns = blockIdx.z;
  int d = blockIdx.x*1024 + threadIdx.x*4;
  const float4* src = (const float4*)(x + (size_t)b*N_*D_ + (size_t)ns*128*D_ + d);
  __nv_bfloat162* dst = (__nv_bfloat162*)(g_xb + (size_t)b*N_*D_ + (size_t)ns*128*D_ + d);
  float s0=0.f,s1=0.f,s2=0.f,s3=0.f;
  for(int n=0;n<128;n++){
    float4 v = src[(size_t)n*(D_/4)];
    s0+=v.x; s1+=v.y; s2+=v.z; s3+=v.w;
    dst[(size_t)n*(D_/2)  ] = __floats2bfloat162_rn(v.x,v.y);
    dst[(size_t)n*(D_/2)+1] = __floats2bfloat162_rn(v.z,v.w);
  }
  *(float4*)(g_xpart + ((size_t)(ns*B_+b))*D_ + d) = make_float4(s0,s1,s2,s3);
}

// ---------------- Kernel 2: W fp32 -> bf16 (all three in one launch) ----------------
__global__ void k_wcvt(const float4* __restrict__ Wq, const float4* __restrict__ Wk,
                       const float4* __restrict__ Wv){
  int z = blockIdx.y;
  const float4* src = z==0 ? Wq : (z==1 ? Wk : Wv);
  __nv_bfloat162* dst = (__nv_bfloat162*)(z==0 ? g_Wqb : (z==1 ? g_Wkb : g_Wvb));
  int i = blockIdx.x*256 + threadIdx.x;
  float4 v = src[i];
  dst[2*i  ] = __floats2bfloat162_rn(v.x, v.y);
  dst[2*i+1] = __floats2bfloat162_rn(v.z, v.w);
}

// ---------------- Kernel 3a/3b: S[b] = xsum[b] @ Wv + 2048*bv (exact fp32, split) ----------------
__global__ void k_sproj1(const float* __restrict__ Wv){
  __shared__ float xs[256];
  int b = blockIdx.x, ds = blockIdx.y, e = threadIdx.x;
  {
    float s = 0.f;
    #pragma unroll
    for(int ns=0;ns<16;ns++) s += g_xpart[(size_t)(ns*B_ + b)*D_ + ds*256 + e];
    xs[e] = s;
  }
  __syncthreads();
  const float* Wp = Wv + (size_t)ds*256*E_ + e;
  float a0=0.f,a1=0.f,a2=0.f,a3=0.f;
  for(int d=0;d<256;d+=4){
    a0 += xs[d  ]*Wp[(size_t)(d  )*E_];
    a1 += xs[d+1]*Wp[(size_t)(d+1)*E_];
    a2 += xs[d+2]*Wp[(size_t)(d+2)*E_];
    a3 += xs[d+3]*Wp[(size_t)(d+3)*E_];
  }
  g_spart[(ds*B_+b)*E_ + e] = (a0+a1)+(a2+a3);
}
__global__ void k_sproj2(const float* __restrict__ bv){
  int b = blockIdx.x, e = threadIdx.x;
  float s = 2048.0f*bv[e];
  #pragma unroll
  for(int ds=0;ds<8;ds++) s += g_spart[(ds*B_+b)*E_ + e];
  g_S[b*E_+e] = s;
}

// ---------------- Kernel 4: QKV = xb @ W + b (z-merged; bf16 HMMA, CTA 128x256, warp 64x64) ----------------
#define QK_A_OFF 4096
#define QK_B_OFF (QK_A_OFF + 2*128*80)
#define QK_SMEM (QK_B_OFF + 2*32*528)

__global__ __launch_bounds__(256) void k_qkv(
    const float* __restrict__ bq, const float* __restrict__ bk, const float* __restrict__ bv)
{
  extern __shared__ char qs[];
  unsigned sb = smem_u32(qs);
  float* biass = (float*)qs;   // [3][256]

  int m0 = blockIdx.x*128;
  int tid = threadIdx.x;
  int w = tid>>5, lane = tid&31, g = lane>>2, tg = lane&3;
  int wm = w>>2, wn = w&3;   // warp tile 64(m) x 64(n)

  biass[tid]       = bq[tid];
  biass[tid + 256] = bk[tid];
  biass[tid + 512] = bv[tid];

  unsigned a_base = sb + QK_A_OFF;
  unsigned b_base = sb + QK_B_OFF;
  const __nv_bfloat16* xsrc = g_xb + (size_t)m0*D_;
  __syncthreads();

  for(int z=0; z<3; z++){
    const __nv_bfloat16* W = z==0 ? g_Wqb : (z==1 ? g_Wkb : g_Wvb);
    __nv_bfloat16* outp = z==0 ? g_Q : (z==1 ? g_K : g_V);
    const float* bs = biass + z*256;

    float acc[4][8][4];
    #pragma unroll
    for(int mt=0;mt<4;mt++)
      #pragma unroll
      for(int nc=0;nc<8;nc++)
        #pragma unroll
        for(int i=0;i<4;i++) acc[mt][nc][i]=0.f;

    // prologue: stage 0
    {
      #pragma unroll
      for(int j=0;j<2;j++){
        int idx = tid + 256*j; int row = idx>>2, c16 = idx&3;
        cp16(a_base + (unsigned)(row*80 + c16*16), xsrc + (size_t)row*D_ + c16*8);
      }
      #pragma unroll
      for(int j=0;j<4;j++){
        int idx = tid + 256*j; int row = idx>>5, c16 = idx&31;
        cp16(b_base + (unsigned)(row*528 + c16*16), W + (size_t)row*E_ + c16*8);
      }
      cp_commit();
    }

    const int KT = D_/32;  // 64
    for(int kt=0; kt<KT; kt++){
      int cur = kt&1;
      if(kt+1 < KT){
        int nxt = cur^1;
        unsigned da = a_base + (unsigned)(nxt*128*80);
        unsigned db = b_base + (unsigned)(nxt*32*528);
        #pragma unroll
        for(int j=0;j<2;j++){
          int idx = tid + 256*j; int row = idx>>2, c16 = idx&3;
          cp16(da + (unsigned)(row*80 + c16*16), xsrc + (size_t)row*D_ + (kt+1)*32 + c16*8);
        }
        #pragma unroll
        for(int j=0;j<4;j++){
          int idx = tid + 256*j; int row = idx>>5, c16 = idx&31;
          cp16(db + (unsigned)(row*528 + c16*16), W + ((size_t)((kt+1)*32+row))*E_ + c16*8);
        }
        cp_commit();
        cp_wait<1>();
      } else {
        cp_wait<0>();
      }
      __syncthreads();

      unsigned ac = a_base + (unsigned)(cur*128*80);
      unsigned bc = b_base + (unsigned)(cur*32*528);
      #pragma unroll
      for(int kc=0;kc<2;kc++){
        unsigned a[4][4];
        #pragma unroll
        for(int mt=0;mt<4;mt++){
          int row = wm*64 + mt*16 + (lane&15);
          int col = kc*16 + (lane>>4)*8;
          ldsm_x4(a[mt], ac + (unsigned)(row*80 + col*2));
        }
        #pragma unroll
        for(int nb=0;nb<4;nb++){
          unsigned r[4];
          int row = kc*16 + (lane&7) + ((lane>>3)&1)*8;
          int col = wn*64 + nb*16 + (lane>>4)*8;
          ldsm_x4_t(r, bc + (unsigned)(row*528 + col*2));
          #pragma unroll
          for(int mt=0;mt<4;mt++){
            mma_bf16(acc[mt][2*nb  ], a[mt], r[0], r[1]);
            mma_bf16(acc[mt][2*nb+1], a[mt], r[2], r[3]);
          }
        }
      }
      __syncthreads();
    }

    // epilogue: +bias, store bf16
    #pragma unroll
    for(int mt=0;mt<4;mt++){
      int r0 = m0 + wm*64 + mt*16 + g;
      #pragma unroll
      for(int nc=0;nc<8;nc++){
        int c = wn*64 + nc*8 + 2*tg;
        float b0 = bs[c], b1 = bs[c+1];
        *(__nv_bfloat162*)(outp + (size_t)r0*E_ + c) =
          __floats2bfloat162_rn(acc[mt][nc][0]+b0, acc[mt][nc][1]+b1);
        *(__nv_bfloat162*)(outp + (size_t)(r0+8)*E_ + c) =
          __floats2bfloat162_rn(acc[mt][nc][2]+b0, acc[mt][nc][3]+b1);
      }
    }
  }
}

// ---------------- Kernel 5: flash attention, Q tile 128 rows, e = 1 + p decomposition ----------------
#define A_BM 128
#define A_BN 64
#define QKST 264   // 528B rows for Q/K/V tiles
#define PST  72    // 144B rows for P
#define AQ_OFF 0
#define AK_OFF (128*QKST)
#define AV_OFF (AK_OFF + 2*64*QKST)
#define AP_OFF (AV_OFF + 2*64*QKST)
#define A_BF_TOT (AP_OFF + 128*PST)
#define A_SMEM (A_BF_TOT*2 + (128+256)*4)

__global__ __launch_bounds__(256,1) void k_attn(float* __restrict__ out){
  extern __shared__ __nv_bfloat16 sma[];
  float* Zs = (float*)(sma + A_BF_TOT);   // [128]
  float* Ss = Zs + 128;                   // [256]

  int bb = blockIdx.y;
  int n0 = blockIdx.x*A_BM;
  int tid = threadIdx.x;
  int w = tid>>5, lane = tid&31, g = lane>>2, tg = lane&3;
  int swm = w&3, swn = w>>2;   // scores: 32x32 warp tiles (4m x 2n); PV: 32x128 (same mapping)

  if(tid < 128) Zs[tid] = 0.0f;
  Ss[tid] = g_S[bb*E_ + tid];

  unsigned q_base = smem_u32(sma + AQ_OFF);
  unsigned k_base = smem_u32(sma + AK_OFF);
  unsigned v_base = smem_u32(sma + AV_OFF);
  unsigned p_base = smem_u32(sma + AP_OFF);

  // prologue: Q tile (128 rows) + KV block 0
  {
    const __nv_bfloat16* qsrc = g_Q + ((size_t)(bb*N_ + n0))*E_;
    const __nv_bfloat16* ksrc = g_K + ((size_t)bb*N_)*E_;
    const __nv_bfloat16* vsrc = g_V + ((size_t)bb*N_)*E_;
    #pragma unroll
    for(int j=0;j<16;j++){
      int idx = tid + 256*j; int row = idx>>5, c16 = idx&31;
      cp16(q_base + (unsigned)(row*528 + c16*16), qsrc + (size_t)row*E_ + c16*8);
    }
    #pragma unroll
    for(int j=0;j<8;j++){
      int idx = tid + 256*j; int row = idx>>5, c16 = idx&31;
      unsigned off = (unsigned)(row*528 + c16*16);
      size_t soff = (size_t)row*E_ + c16*8;
      cp16(k_base + off, ksrc + soff);
      cp16(v_base + off, vsrc + soff);
    }
    cp_commit();
  }

  float oacc[2][16][4];
  #pragma unroll
  for(int mt=0;mt<2;mt++)
    #pragma unroll
    for(int nc=0;nc<16;nc++)
      #pragma unroll
      for(int i=0;i<4;i++) oacc[mt][nc][i]=0.f;

  const int KB = N_/A_BN;  // 32
  for(int kb=0; kb<KB; kb++){
    int cur = kb&1;
    if(kb+1 < KB){
      int nxt = cur^1;
      unsigned dk = k_base + (unsigned)(nxt*64*QKST*2);
      unsigned dv = v_base + (unsigned)(nxt*64*QKST*2);
      const __nv_bfloat16* ksrc = g_K + ((size_t)(bb*N_ + (kb+1)*A_BN))*E_;
      const __nv_bfloat16* vsrc = g_V + ((size_t)(bb*N_ + (kb+1)*A_BN))*E_;
      #pragma unroll
      for(int j=0;j<8;j++){
        int idx = tid + 256*j; int row = idx>>5, c16 = idx&31;
        unsigned off = (unsigned)(row*528 + c16*16);
        size_t soff = (size_t)row*E_ + c16*8;
        cp16(dk + off, ksrc + soff);
        cp16(dv + off, vsrc + soff);
      }
      cp_commit();
      cp_wait<1>();
    } else {
      cp_wait<0>();
    }
    __syncthreads();

    unsigned kc_base = k_base + (unsigned)(cur*64*QKST*2);
    unsigned vc_base = v_base + (unsigned)(cur*64*QKST*2);

    // ---- scores: 128x64, warp tile 32x32 ----
    float sc[2][4][4];
    #pragma unroll
    for(int mt=0;mt<2;mt++)
      #pragma unroll
      for(int nc=0;nc<4;nc++)
        #pragma unroll
        for(int i=0;i<4;i++) sc[mt][nc][i]=0.f;

    #pragma unroll
    for(int kc=0;kc<16;kc++){
      unsigned a[2][4];
      #pragma unroll
      for(int mt=0;mt<2;mt++){
        int row = swm*32 + mt*16 + (lane&15);
        int col = kc*16 + (lane>>4)*8;
        ldsm_x4(a[mt], q_base + (unsigned)(row*528 + col*2));
      }
      #pragma unroll
      for(int nb=0;nb<2;nb++){
        unsigned r[4];
        int row = swn*32 + nb*16 + (lane&15);
        int col = kc*16 + (lane>>4)*8;
        ldsm_x4(r, kc_base + (unsigned)(row*528 + col*2));
        #pragma unroll
        for(int mt=0;mt<2;mt++){
          mma_bf16(sc[mt][2*nb  ], a[mt], r[0], r[2]);
          mma_bf16(sc[mt][2*nb+1], a[mt], r[1], r[3]);
        }
      }
    }

    // ---- p = expm1(sigmoid(s)/16); Z row sums; store P bf16 ----
    #pragma unroll
    for(int mt=0;mt<2;mt++){
      float zlo=0.f, zhi=0.f;
      #pragma unroll
      for(int nc=0;nc<4;nc++){
        #pragma unroll
        for(int i=0;i<4;i++){
          float s = sc[mt][nc][i];
          float sig = __fdividef(1.0f, 1.0f + __expf(-s));
          float gg = 0.0625f * sig;
          sc[mt][nc][i] = gg*fmaf(gg, fmaf(gg, fmaf(gg, 0.041666668f, 0.16666667f), 0.5f), 1.0f);
        }
        zlo += sc[mt][nc][0]+sc[mt][nc][1];
        zhi += sc[mt][nc][2]+sc[mt][nc][3];
      }
      zlo += __shfl_xor_sync(0xffffffffu, zlo, 1);
      zlo += __shfl_xor_sync(0xffffffffu, zlo, 2);
      zhi += __shfl_xor_sync(0xffffffffu, zhi, 1);
      zhi += __shfl_xor_sync(0xffffffffu, zhi, 2);
      if(tg==0){
        atomicAdd(&Zs[swm*32+mt*16+g],   zlo);
        atomicAdd(&Zs[swm*32+mt*16+g+8], zhi);
      }
      #pragma unroll
      for(int nc=0;nc<4;nc++){
        int c = swn*32 + nc*8 + 2*tg;
        *(__nv_bfloat162*)((char*)sma + AP_OFF*2 + (swm*32+mt*16+g  )*144 + c*2) =
          __floats2bfloat162_rn(sc[mt][nc][0], sc[mt][nc][1]);
        *(__nv_bfloat162*)((char*)sma + AP_OFF*2 + (swm*32+mt*16+g+8)*144 + c*2) =
          __floats2bfloat162_rn(sc[mt][nc][2], sc[mt][nc][3]);
      }
    }
    // pair barrier: P rows [swm*32, swm*32+32) produced by warps {swm, swm+4}
    bar_pair(1+swm);

    // ---- out += P @ V : P 128x64, V 64x256, warp tile 32x128 ----
    #pragma unroll
    for(int kc=0;kc<4;kc++){
      unsigned pa[2][4];
      #pragma unroll
      for(int mt=0;mt<2;mt++){
        int row = swm*32 + mt*16 + (lane&15);
        int col = kc*16 + (lane>>4)*8;
        ldsm_x4(pa[mt], p_base + (unsigned)(row*144 + col*2));
      }
      #pragma unroll
      for(int nb=0;nb<8;nb++){
        unsigned r[4];
        int row = kc*16 + (lane&7) + ((lane>>3)&1)*8;
        int col = swn*128 + nb*16 + (lane>>4)*8;
        ldsm_x4_t(r, vc_base + (unsigned)(row*528 + col*2));
        #pragma unroll
        for(int mt=0;mt<2;mt++){
          mma_bf16(oacc[mt][2*nb  ], pa[mt], r[0], r[1]);
          mma_bf16(oacc[mt][2*nb+1], pa[mt], r[2], r[3]);
        }
      }
    }
    // pair barrier: P consumers done before next iteration overwrites P
    bar_pair(1+swm);
  }

  // epilogue: out = (S + acc) / (2048 + Z)
  #pragma unroll
  for(int mt=0;mt<2;mt++){
    int r = swm*32 + mt*16 + g;
    float rz0 = __fdividef(1.0f, 2048.0f + Zs[r]);
    float rz1 = __fdividef(1.0f, 2048.0f + Zs[r+8]);
    #pragma unroll
    for(int nc=0;nc<16;nc++){
      int c = swn*128 + nc*8 + 2*tg;
      float s0 = Ss[c], s1 = Ss[c+1];
      float2 y0 = make_float2((s0+oacc[mt][nc][0])*rz0, (s1+oacc[mt][nc][1])*rz0);
      float2 y1 = make_float2((s0+oacc[mt][nc][2])*rz1, (s1+oacc[mt][nc][3])*rz1);
      *(float2*)(out + ((size_t)(bb*N_ + n0 + r  ))*E_ + c) = y0;
      *(float2*)(out + ((size_t)(bb*N_ + n0 + r+8))*E_ + c) = y1;
    }
  }
}

extern "C" void kernel_launch(void* const* d_in, const int* in_sizes, int n_in,
                              void* d_out, int out_size){
  const float* x  = (const float*)d_in[0];
  const float* Wq = (const float*)d_in[1];
  const float* bq = (const float*)d_in[2];
  const float* Wk = (const float*)d_in[3];
  const float* bk = (const float*)d_in[4];
  const float* Wv = (const float*)d_in[5];
  const float* bv = (const float*)d_in[6];
  float* out = (float*)d_out;

  cudaFuncSetAttribute(k_qkv,  cudaFuncAttributeMaxDynamicSharedMemorySize, QK_SMEM);
  cudaFuncSetAttribute(k_attn, cudaFuncAttributeMaxDynamicSharedMemorySize, A_SMEM);

  // staging
  k_xcvt<<<dim3(2, B_, 16), 256>>>(x);
  k_wcvt<<<dim3(D_*E_/4/256, 3), 256>>>((const float4*)Wq, (const float4*)Wk, (const float4*)Wv);

  // exact fp32 S = sum_m v_m (split over 64 CTAs, two-stage deterministic)
  k_sproj1<<<dim3(B_, 8), 256>>>(Wv);
  k_sproj2<<<B_, 256>>>(bv);

  // bf16 QKV projection (HMMA, z-merged: one CTA computes Q,K,V for its m-tile)
  k_qkv<<<dim3(M_TOTAL/128, 1, 1), 256, QK_SMEM>>>(bq, bk, bv);

  // bf16 flash attention (HMMA, 128-row Q tiles, single wave, pair barriers)
  k_attn<<<dim3(N_/A_BM, B_), 256, A_SMEM>>>(out);
}